// round 9
// baseline (speedup 1.0000x reference)
#include <cuda_runtime.h>

#define NN 10000
#define EE 50000
#define NC 25
#define EPG 10232
#define NPG 12224

typedef unsigned long long u64;

__constant__ int c_lof[NC] = {0,1,1,1,2,2,2,2,2,3,3,3,3,3,3,3,4,4,4,4,4,4,4,4,4};

__device__ float    g_h[(size_t)NN*1600];
__device__ float    g_r[(size_t)EE*640];
__device__ float    g_msg[(size_t)EE*1600];
__device__ float    g_alpha[EE*8];
__device__ int      g_cnt[NN];
__device__ int      g_rp[NN+1];
__device__ int      g_cur[NN];
__device__ int      g_ce[EE];

__device__ __forceinline__ float silu(float x){ return x/(1.f+__expf(-x)); }
__device__ __forceinline__ float4 silu4(float4 v){
  return make_float4(silu(v.x),silu(v.y),silu(v.z),silu(v.w));
}
// ---- packed f32x2 helpers (FFMA2 path) ----
__device__ __forceinline__ u64 bc2(float s){
  unsigned i=__float_as_uint(s); u64 r;
  asm("mov.b64 %0,{%1,%1};" : "=l"(r) : "r"(i)); return r;
}
__device__ __forceinline__ void f2(u64&a, u64 v, u64 s){
  asm("fma.rn.f32x2 %0,%1,%2,%0;" : "+l"(a) : "l"(v), "l"(s));
}
__device__ __forceinline__ void m2(u64&a, u64 v){
  asm("mul.rn.f32x2 %0,%0,%1;" : "+l"(a) : "l"(v));
}
__device__ __forceinline__ void padd(u64&a, u64 b){
  asm("add.rn.f32x2 %0,%0,%1;" : "+l"(a) : "l"(b));
}
union F4U { float4 f; ulonglong2 u; };
__device__ __forceinline__ float4 tof4(ulonglong2 a){ F4U u; u.u=a; return u.f; }
__device__ __forceinline__ ulonglong2 tou2(float4 f){ F4U u; u.f=f; return u.u; }
#define FMAP(a,v,s) { f2((a).x,(v).x,(s)); f2((a).y,(v).y,(s)); }
#define FMA4(a,s,v) { (a).x=fmaf((s),(v).x,(a).x); (a).y=fmaf((s),(v).y,(a).y); \
                      (a).z=fmaf((s),(v).z,(a).z); (a).w=fmaf((s),(v).w,(a).w); }
#define MUL4(a,v)   { (a).x*=(v).x; (a).y*=(v).y; (a).z*=(v).z; (a).w*=(v).w; }
#define Z4 make_float4(0.f,0.f,0.f,0.f)
#define ZP2 {0ull,0ull}
#define GBAR() asm volatile("bar.sync %0, %1;" :: "r"(grp+1), "r"(256) : "memory")

// ---------------- rmsnorm1 ----------------
__global__ void k_rms1(const float* __restrict__ x, const float* __restrict__ gamma){
  int n = blockIdx.x*4 + threadIdx.y;
  if(n >= NN) return;
  int c = threadIdx.x;
  const float* xp = x + (size_t)n*1600 + c;
  float s = 0.f;
  #pragma unroll
  for(int i=0;i<NC;i++){ float v = xp[i*64]; s += v*v; }
  float gm = rsqrtf(s*(1.f/25.f) + 1e-6f) * gamma[c];
  float* hp = g_h + (size_t)n*1600 + c;
  #pragma unroll
  for(int i=0;i<NC;i++) hp[i*64] = xp[i*64]*gm;
}

// ---------------- CSR build ----------------
__global__ void k_count(const int* __restrict__ ei){
  int e = blockIdx.x*256 + threadIdx.x;
  if(e < EE) atomicAdd(&g_cnt[ei[EE+e]], 1);
}
__global__ void k_scan(){
  __shared__ int ps[1024];
  int t = threadIdx.x;
  int v[10]; int s = 0;
  #pragma unroll
  for(int m=0;m<10;m++){ int i=t*10+m; int c=(i<NN)? g_cnt[i]:0; v[m]=s; s+=c; }
  ps[t]=s; __syncthreads();
  for(int off=1; off<1024; off<<=1){
    int val=(t>=off)? ps[t-off]:0; __syncthreads();
    ps[t]+=val; __syncthreads();
  }
  int excl=(t>0)? ps[t-1]:0;
  #pragma unroll
  for(int m=0;m<10;m++){
    int i=t*10+m;
    if(i<NN){ int o=excl+v[m]; g_rp[i]=o; g_cur[i]=o; }
  }
  if(t==0) g_rp[NN]=EE;
}
__global__ void k_fill(const int* __restrict__ ei){
  int e = blockIdx.x*256 + threadIdx.x;
  if(e < EE) g_ce[atomicAdd(&g_cur[ei[EE+e]],1)] = e;
}

// ---------------- radial MLP ----------------
__global__ __launch_bounds__(256,1)
void k_rad(const float* __restrict__ ed, const int* __restrict__ ei,
           const int* __restrict__ zn,
           const float* __restrict__ st, const float* __restrict__ tt,
           const float* __restrict__ w1, const float* __restrict__ b1,
           const float* __restrict__ w2, const float* __restrict__ b2,
           const float* __restrict__ w3, const float* __restrict__ b3)
{
  extern __shared__ float sm[];
  float* sw1=sm; float* sw2=sw1+6144; float* sw3=sw2+4096;
  float* sb1=sw3+40960; float* sb2=sb1+64; float* sb3=sb2+64;
  float* ef=sb3+640; float* h1=ef+384; float* h2=h1+256;
  int tid=threadIdx.x;
  for(int i=tid;i<6144;i+=256)  sw1[i]=w1[i];
  for(int i=tid;i<4096;i+=256)  sw2[i]=w2[i];
  for(int i=tid;i<40960;i+=256) sw3[i]=w3[i];
  if(tid<64){ sb1[tid]=b1[tid]; sb2[tid]=b2[tid]; }
  for(int i=tid;i<640;i+=256)   sb3[i]=b3[i];
  __syncthreads();

  int grp=tid>>6, t=tid&63;
  int q=grp;
  int nm=(q<2)?3:2;
  int m0=q, m1=q+4, m2=q+8;

  int iters=(EE+(int)gridDim.x*4-1)/((int)gridDim.x*4);
  for(int it=0; it<iters; it++){
    int e0=(it*(int)gridDim.x+(int)blockIdx.x)*4;
    int e=e0+grp;
    bool valid=(e<EE);
    if(t<32){
      if(valid){
        int src=ei[e], dst=ei[EE+e];
        ef[grp*96+t]   =ed[(size_t)e*32+t];
        ef[grp*96+32+t]=st[zn[src]*32+t];
        ef[grp*96+64+t]=tt[zn[dst]*32+t];
      } else {
        ef[grp*96+t]=0.f; ef[grp*96+32+t]=0.f; ef[grp*96+64+t]=0.f;
      }
    }
    __syncthreads();
    {
      float acc=sb1[t];
      const float4* ef4=(const float4*)(ef+grp*96);
      #pragma unroll
      for(int k4=0;k4<24;k4++){
        float4 v=ef4[k4];
        acc=fmaf(v.x,sw1[(k4*4+0)*64+t],acc);
        acc=fmaf(v.y,sw1[(k4*4+1)*64+t],acc);
        acc=fmaf(v.z,sw1[(k4*4+2)*64+t],acc);
        acc=fmaf(v.w,sw1[(k4*4+3)*64+t],acc);
      }
      h1[grp*64+t]=silu(acc);
    }
    __syncthreads();
    {
      float acc=sb2[t];
      const float4* h14=(const float4*)(h1+grp*64);
      #pragma unroll
      for(int k4=0;k4<16;k4++){
        float4 v=h14[k4];
        acc=fmaf(v.x,sw2[(k4*4+0)*64+t],acc);
        acc=fmaf(v.y,sw2[(k4*4+1)*64+t],acc);
        acc=fmaf(v.z,sw2[(k4*4+2)*64+t],acc);
        acc=fmaf(v.w,sw2[(k4*4+3)*64+t],acc);
      }
      h2[grp*64+t]=silu(acc);
    }
    __syncthreads();
    {
      float a0[4], a1[4], a2[4];
      #pragma unroll
      for(int ee=0;ee<4;ee++){ a0[ee]=sb3[t+64*m0]; a1[ee]=sb3[t+64*m1]; a2[ee]=(nm==3)?sb3[t+64*m2]:0.f; }
      for(int k=0;k<64;k++){
        float hh0=h2[k], hh1=h2[64+k], hh2v=h2[128+k], hh3=h2[192+k];
        float wA=sw3[k*640+t+64*m0];
        float wB=sw3[k*640+t+64*m1];
        a0[0]=fmaf(wA,hh0,a0[0]); a0[1]=fmaf(wA,hh1,a0[1]); a0[2]=fmaf(wA,hh2v,a0[2]); a0[3]=fmaf(wA,hh3,a0[3]);
        a1[0]=fmaf(wB,hh0,a1[0]); a1[1]=fmaf(wB,hh1,a1[1]); a1[2]=fmaf(wB,hh2v,a1[2]); a1[3]=fmaf(wB,hh3,a1[3]);
        if(nm==3){
          float wC=sw3[k*640+t+64*m2];
          a2[0]=fmaf(wC,hh0,a2[0]); a2[1]=fmaf(wC,hh1,a2[1]); a2[2]=fmaf(wC,hh2v,a2[2]); a2[3]=fmaf(wC,hh3,a2[3]);
        }
      }
      #pragma unroll
      for(int ee=0;ee<4;ee++){
        int eo=e0+ee;
        if(eo<EE){
          g_r[(size_t)eo*640+t+64*m0]=a0[ee];
          g_r[(size_t)eo*640+t+64*m1]=a1[ee];
          if(nm==3) g_r[(size_t)eo*640+t+64*m2]=a2[ee];
        }
      }
    }
    __syncthreads();
  }
}

// ---------------- per-edge kernel: prefetch pipeline + FFMA2 ----------------
__global__ __launch_bounds__(512,1)
void k_edge(const float* __restrict__ wigner, const int* __restrict__ ei,
            const float* __restrict__ W1, const float* __restrict__ W0,
            const float* __restrict__ adot, const float* __restrict__ tg,
            const float* __restrict__ fg)
{
  extern __shared__ float sm[];
  float* sW1 = sm;          // 8192
  float* sW0 = sW1+8192;    // 24576 transposed
  float* sTG = sW0+24576;   // 900
  float* sFG = sTG+900;     // 900
  float* sAD = sFG+900;     // 128
  float* pe  = sAD+128;     // 2 * EPG
  int tid=threadIdx.x;
  for(int i=tid;i<8192;i+=512) sW1[i]=W1[i];
  for(int i=tid;i<24576;i+=512){ int o=i>>7,c=i&127; sW0[i]=W0[c*192+o]; }
  for(int i=tid;i<900;i+=512){ sTG[i]=tg[i]; sFG[i]=fg[i]; }
  if(tid<128) sAD[tid]=adot[tid];
  __syncthreads();

  int grp = tid>>8, t = tid&255;
  float* base  = pe + grp*EPG;
  float* swigA = base;
  float* swigB = base+700;
  float* scat  = base+1400;
  float* srr   = base+4600;
  float* sxe   = base+5240;
  float* sextra= base+8440;
  float* smsg  = base+8632;
  float* sgrid = sxe;
  float* smact = smsg;

  int c4=t&31, rg8=t>>5;
  int h4=t&15, rg16=t>>4;

  int stride = (int)gridDim.x*2;
  int e = (int)blockIdx.x*2 + grp;
  int p = 0;

  {
    const float* wp=wigner+(size_t)e*625;
    for(int i=t;i<625;i+=256) swigA[(i/25)*28+(i%25)]=wp[i];
    int src=ei[e], dst=ei[EE+e];
    const float4* hs=(const float4*)(g_h+(size_t)src*1600);
    const float4* hd=(const float4*)(g_h+(size_t)dst*1600);
    float4* cat4=(float4*)scat;
    for(int i=t;i<800;i+=256){ int j=i>>5,qq=i&31; cat4[i]=(qq<16)?hs[j*16+qq]:hd[j*16+qq-16]; }
    const float4* rp4=(const float4*)(g_r+(size_t)e*640);
    float4* srr4=(float4*)srr;
    for(int i=t;i<160;i+=256) srr4[i]=rp4[i];
  }

  for(; e<EE; e+=stride){
    int en = e + stride; if(en >= EE) en = e;
    float* swig  = p? swigB : swigA;
    float* swigN = p? swigA : swigB;
    GBAR();

    // xe = (wig @ cat) * r[EXPAND]  (FFMA2)
    {
      const ulonglong2* catp=(const ulonglong2*)scat;
      const ulonglong2* r4=(const ulonglong2*)srr;
      ulonglong2* xe2=(ulonglong2*)sxe;
      int r0=rg8, r1=rg8+8, r2=rg8+16;
      ulonglong2 a0=ZP2,a1=ZP2,a2=ZP2,a3=ZP2;
      #pragma unroll
      for(int j4=0;j4<6;j4++){
        float4 w0=*(const float4*)&swig[r0*28+j4*4];
        float4 w1v=*(const float4*)&swig[r1*28+j4*4];
        float4 w2v=*(const float4*)&swig[r2*28+j4*4];
        float4 w3v=*(const float4*)&swig[24*28+j4*4];
        #pragma unroll
        for(int tt2=0;tt2<4;tt2++){
          ulonglong2 cv=catp[(j4*4+tt2)*32+c4];
          u64 s0=bc2(((const float*)&w0)[tt2]);
          u64 s1=bc2(((const float*)&w1v)[tt2]);
          u64 s2=bc2(((const float*)&w2v)[tt2]);
          FMAP(a0,cv,s0); FMAP(a1,cv,s1); FMAP(a2,cv,s2);
          if(rg8==0){ u64 s3=bc2(((const float*)&w3v)[tt2]); FMAP(a3,cv,s3); }
        }
      }
      { ulonglong2 cv=catp[24*32+c4];
        u64 s0=bc2(swig[r0*28+24]), s1=bc2(swig[r1*28+24]), s2=bc2(swig[r2*28+24]);
        FMAP(a0,cv,s0); FMAP(a1,cv,s1); FMAP(a2,cv,s2);
        if(rg8==0){ u64 s3=bc2(swig[24*28+24]); FMAP(a3,cv,s3); }
      }
      ulonglong2 rv;
      rv=r4[c_lof[r0]*32+c4]; m2(a0.x,rv.x); m2(a0.y,rv.y); xe2[r0*32+c4]=a0;
      rv=r4[c_lof[r1]*32+c4]; m2(a1.x,rv.x); m2(a1.y,rv.y); xe2[r1*32+c4]=a1;
      rv=r4[c_lof[r2]*32+c4]; m2(a2.x,rv.x); m2(a2.y,rv.y); xe2[r2*32+c4]=a2;
      if(rg8==0){ rv=r4[4*32+c4]; m2(a3.x,rv.x); m2(a3.y,rv.y); xe2[24*32+c4]=a3; }
    }
    GBAR();

    // prefetch next edge
    {
      const float* wp=wigner+(size_t)en*625;
      for(int i=t;i<625;i+=256) swigN[(i/25)*28+(i%25)]=wp[i];
      int nsrc=ei[en], ndst=ei[EE+en];
      const float4* hs=(const float4*)(g_h+(size_t)nsrc*1600);
      const float4* hd=(const float4*)(g_h+(size_t)ndst*1600);
      float4* cat4=(float4*)scat;
      for(int i=t;i<800;i+=256){ int j=i>>5,qq=i&31; cat4[i]=(qq<16)?hs[j*16+qq]:hd[j*16+qq-16]; }
      const float4* rp4=(const float4*)(g_r+(size_t)en*640);
      float4* srr4=(float4*)srr;
      for(int i=t;i<160;i+=256) srr4[i]=rp4[i];
    }

    // msg = xe @ W1 (FFMA2)  + extra by t<192
    {
      int r0=rg16, r1=rg16+16; bool v1=(r1<25);
      const float4* x0=(const float4*)(sxe+r0*128);
      const float4* x1=(const float4*)(sxe+(v1?r1:0)*128);
      const ulonglong2* w4=(const ulonglong2*)sW1;
      ulonglong2 a0=ZP2,a1=ZP2;
      #pragma unroll 8
      for(int ci=0;ci<32;ci++){
        float4 xv0=x0[ci], xv1=x1[ci];
        #pragma unroll
        for(int tt2=0;tt2<4;tt2++){
          ulonglong2 wv=w4[(ci*4+tt2)*16+h4];
          u64 s0=bc2(((const float*)&xv0)[tt2]);
          u64 s1=bc2(((const float*)&xv1)[tt2]);
          FMAP(a0,wv,s0); FMAP(a1,wv,s1);
        }
      }
      ((ulonglong2*)smsg)[r0*16+h4]=a0;
      if(v1) ((ulonglong2*)smsg)[r1*16+h4]=a1;
    }
    if(t<192){
      const float4* x0=(const float4*)sxe;
      const float4* w=(const float4*)(sW0+t*128);
      float4 acc=Z4;
      #pragma unroll 8
      for(int k=0;k<32;k++){ float4 xv=x0[k], wv=w[k];
        acc.x=fmaf(xv.x,wv.x,acc.x); acc.y=fmaf(xv.y,wv.y,acc.y);
        acc.z=fmaf(xv.z,wv.z,acc.z); acc.w=fmaf(xv.w,wv.w,acc.w); }
      sextra[t]=acc.x+acc.y+acc.z+acc.w;
    }
    GBAR();

    // grid = silu(to_grid @ msg) (FFMA2)  + alpha by t<8
    if(t<8){
      float acc=0.f;
      #pragma unroll
      for(int a=0;a<16;a++){ float v=sextra[t*16+a]; acc=fmaf(silu(v),sAD[t*16+a],acc); }
      g_alpha[e*8+t]=acc;
    }
    {
      int g0=rg16, g1=rg16+16, g2v=rg16+32; bool v2=(g2v<36);
      const ulonglong2* m4=(const ulonglong2*)smsg;
      float4* gr4=(float4*)sgrid;
      ulonglong2 a0=ZP2,a1=ZP2,a2=ZP2;
      #pragma unroll
      for(int i=0;i<25;i++){
        ulonglong2 mv=m4[i*16+h4];
        u64 s0=bc2(sTG[g0*25+i]), s1=bc2(sTG[g1*25+i]);
        FMAP(a0,mv,s0); FMAP(a1,mv,s1);
        if(v2){ u64 s2=bc2(sTG[g2v*25+i]); FMAP(a2,mv,s2); }
      }
      gr4[g0*16+h4]=silu4(tof4(a0));
      gr4[g1*16+h4]=silu4(tof4(a1));
      if(v2) gr4[g2v*16+h4]=silu4(tof4(a2));
    }
    GBAR();

    // mact = [silu(gate); from_grid @ grid] (FFMA2)
    {
      int r0=rg16, r1=rg16+16; bool v1=(r1<25);
      const ulonglong2* gr4=(const ulonglong2*)sgrid;
      ulonglong2 a0=ZP2,a1=ZP2;
      #pragma unroll 6
      for(int g=0;g<36;g++){
        ulonglong2 gv=gr4[g*16+h4];
        if(rg16>0){ u64 s0=bc2(sFG[r0*36+g]); FMAP(a0,gv,s0); }
        if(v1){ u64 s1=bc2(sFG[r1*36+g]); FMAP(a1,gv,s1); }
      }
      if(rg16==0) a0=tou2(silu4(((const float4*)(sextra+128))[h4]));
      ((ulonglong2*)smact)[r0*16+h4]=a0;
      if(v1) ((ulonglong2*)smact)[r1*16+h4]=a1;
    }
    GBAR();

    // rotated = wig^T @ mact (FFMA2) -> global
    {
      int r0=rg16, r1=rg16+16; bool v1=(r1<25);
      const ulonglong2* m4=(const ulonglong2*)smact;
      ulonglong2 a0=ZP2,a1=ZP2;
      #pragma unroll
      for(int j=0;j<25;j++){
        ulonglong2 mv=m4[j*16+h4];
        u64 s0=bc2(swig[j*28+r0]); FMAP(a0,mv,s0);
        if(v1){ u64 s1=bc2(swig[j*28+r1]); FMAP(a1,mv,s1); }
      }
      ulonglong2* op=(ulonglong2*)(g_msg+(size_t)e*1600);
      op[r0*16+h4]=a0;
      if(v1) op[r1*16+h4]=a1;
    }
    p ^= 1;
  }
}

// ---------------- node: fused softmax + gather + proj + rmsnorm2 + FFN ----------------
__global__ __launch_bounds__(512,1)
void k_node(const float* __restrict__ x, float* __restrict__ out,
            const float* __restrict__ po, const float* __restrict__ g2w,
            const float* __restrict__ glw, const float* __restrict__ glb,
            const float* __restrict__ fw1, const float* __restrict__ fb1,
            const float* __restrict__ fw2, const float* __restrict__ fb2,
            const float* __restrict__ tg, const float* __restrict__ fg)
{
  extern __shared__ float sm[];
  float* sPO  = sm;           // 4096
  float* sGL  = sPO+4096;     // 8192
  float* sW1f = sGL+8192;     // 8192
  float* sW2  = sW1f+8192;    // 8192
  float* sTG  = sW2+8192;     // 900
  float* sFG  = sTG+900;      // 900
  float* sGLB = sFG+900;      // 128
  float* sB1  = sGLB+128;     // 128
  float* sB2  = sB1+128;      // 64
  float* sGam = sB2+64;       // 64
  float* pn   = sGam+64;      // 2 * NPG
  int tid=threadIdx.x;
  for(int i=tid;i<4096;i+=512) sPO[i]=po[i];
  for(int i=tid;i<8192;i+=512){ sGL[i]=glw[i]; sW1f[i]=fw1[i]; sW2[i]=fw2[i]; }
  for(int i=tid;i<900;i+=512){ sTG[i]=tg[i]; sFG[i]=fg[i]; }
  if(tid<128){ sGLB[tid]=glb[tid]; sB1[tid]=fb1[tid]; }
  if(tid<64){ sB2[tid]=fb2[tid]; sGam[tid]=g2w[tid]; }
  __syncthreads();

  int grp=tid>>8, t=tid&255;
  float* base = pn + grp*NPG;
  float* sCE  = base;
  float* sAL  = base+64;
  float* sEW  = base+576;
  float* sXN  = base+1088;
  float* sH   = sXN+1600;
  float* sGate= sH+1600;
  float* sF1  = sGate+128;
  float* sG2  = sF1+3200;
  float* sA   = sG2;
  int* sCEi = (int*)sCE;

  int c4=t&15, rg=t>>4;
  int f4=t&31, rg8=t>>5;

  for(int nb=blockIdx.x*2; nb<NN; nb+=gridDim.x*2){
    int n = nb + grp;
    int beg=g_rp[n], end=g_rp[n+1];
    int deg=end-beg;
    float4* sA4=(float4*)sA;
    for(int i=t;i<400;i+=256) sA4[i]=Z4;
    if(t<16) sGate[t] = (t<8)? -3.0e38f : 0.f;
    GBAR();

    for(int k0=beg; k0<end; k0+=64){
      int kc=min(64,end-k0);
      for(int idx=t; idx<kc; idx+=256) sCEi[idx]=g_ce[k0+idx];
      GBAR();
      for(int idx=t; idx<kc*2; idx+=256){
        int j=idx>>1, q=idx&1;
        ((float4*)sAL)[j*2+q] = ((const float4*)(g_alpha+(size_t)sCEi[j]*8))[q];
      }
      GBAR();
      if(t<8){
        float m=sGate[t], s=sGate[8+t];
        for(int j=0;j<kc;j++){
          float a=sAL[j*8+t];
          if(a>m){ s=s*__expf(m-a)+1.f; m=a; }
          else    s+=__expf(a-m);
        }
        sGate[t]=m; sGate[8+t]=s;
      }
      GBAR();
    }
    if(t<8) sGate[8+t]=1.f/(sGate[8+t]+1e-8f);
    GBAR();

    for(int k0=beg; k0<end; k0+=64){
      int kc=min(64,end-k0);
      if(deg>64){
        for(int idx=t; idx<kc; idx+=256) sCEi[idx]=g_ce[k0+idx];
        GBAR();
        for(int idx=t; idx<kc*2; idx+=256){
          int j=idx>>1, q=idx&1;
          ((float4*)sAL)[j*2+q] = ((const float4*)(g_alpha+(size_t)sCEi[j]*8))[q];
        }
      }
      GBAR();
      for(int idx=t; idx<kc*8; idx+=256)
        sEW[idx]=__expf(sAL[idx]-sGate[idx&7])*sGate[8+(idx&7)];
      GBAR();
      for(int j=0;j<kc;j++){
        int e=sCEi[j];
        const float4* mp=(const float4*)(g_msg+(size_t)e*1600);
        const float* wj = sEW + j*8;
        for(int i=t;i<400;i+=256){
          float w=wj[(i&15)>>1];
          float4 v=mp[i];
          float4 a=sA4[i];
          FMA4(a,w,v);
          sA4[i]=a;
        }
      }
      GBAR();
    }

    // XN = x + agg @ proj_out (FFMA2)
    {
      int r0=rg, r1=rg+16; bool v1=(r1<25);
      const float4* x4g=(const float4*)(x+(size_t)n*1600);
      const ulonglong2* p4=(const ulonglong2*)sPO;
      ulonglong2 a0=tou2(x4g[r0*16+c4]);
      ulonglong2 a1=tou2(v1? x4g[r1*16+c4] : Z4);
      #pragma unroll 8
      for(int k=0;k<64;k++){
        ulonglong2 wv=p4[k*16+c4];
        u64 s0=bc2(sA[r0*64+k]); FMAP(a0,wv,s0);
        if(v1){ u64 s1=bc2(sA[r1*64+k]); FMAP(a1,wv,s1); }
      }
      ((ulonglong2*)sXN)[r0*16+c4]=a0;
      if(v1) ((ulonglong2*)sXN)[r1*16+c4]=a1;
    }
    GBAR();
    if(t<64){
      float s=0.f;
      #pragma unroll
      for(int i=0;i<NC;i++){ float v=sXN[i*64+t]; s=fmaf(v,v,s); }
      sGate[t]=rsqrtf(s*(1.f/25.f)+1e-6f)*sGam[t];
    }
    GBAR();
    {
      float4* sH4=(float4*)sH;
      const float4* xn4=(const float4*)sXN;
      const float4* rv4=(const float4*)sGate;
      for(int i=t;i<400;i+=256){ float4 v=xn4[i], r=rv4[i&15]; MUL4(v,r); sH4[i]=v; }
    }
    GBAR();
    float gacc=0.f;
    if(t<128){
      gacc=sGLB[t];
      #pragma unroll 8
      for(int c=0;c<64;c++) gacc=fmaf(sH[c],sGL[c*128+t],gacc);
    }
    GBAR();
    if(t<128) sGate[t]=gacc;
    // F1 = h @ ffn_w1 (+b1 row0) (FFMA2)
    {
      int r0=rg8, r1=rg8+8, r2=rg8+16;
      const ulonglong2* w4=(const ulonglong2*)sW1f;
      ulonglong2 a0=ZP2,a1=ZP2,a2=ZP2,a3=ZP2;
      #pragma unroll 8
      for(int c=0;c<64;c++){
        ulonglong2 wv=w4[c*32+f4];
        u64 s0=bc2(sH[r0*64+c]), s1=bc2(sH[r1*64+c]), s2=bc2(sH[r2*64+c]);
        FMAP(a0,wv,s0); FMAP(a1,wv,s1); FMAP(a2,wv,s2);
        if(rg8==0){ u64 s3=bc2(sH[24*64+c]); FMAP(a3,wv,s3); }
      }
      if(rg8==0){
        ulonglong2 b=tou2(((const float4*)sB1)[f4]);
        padd(a0.x,b.x); padd(a0.y,b.y);
      }
      ulonglong2* F2v=(ulonglong2*)sF1;
      F2v[r0*32+f4]=a0; F2v[r1*32+f4]=a1; F2v[r2*32+f4]=a2;
      if(rg8==0) F2v[24*32+f4]=a3;
    }
    GBAR();
    // G2 = silu(to_grid @ F1) (FFMA2)
    {
      int g0=rg8, g1=rg8+8, g2v=rg8+16, g3=rg8+24, g4v=rg8+32; bool v4=(g4v<36);
      const ulonglong2* F4p=(const ulonglong2*)sF1;
      float4* G4=(float4*)sG2;
      ulonglong2 a0=ZP2,a1=ZP2,a2=ZP2,a3=ZP2,a4=ZP2;
      #pragma unroll
      for(int i=0;i<25;i++){
        ulonglong2 fv=F4p[i*32+f4];
        u64 s0=bc2(sTG[g0*25+i]), s1=bc2(sTG[g1*25+i]);
        u64 s2=bc2(sTG[g2v*25+i]), s3=bc2(sTG[g3*25+i]);
        FMAP(a0,fv,s0); FMAP(a1,fv,s1); FMAP(a2,fv,s2); FMAP(a3,fv,s3);
        if(v4){ u64 s4=bc2(sTG[g4v*25+i]); FMAP(a4,fv,s4); }
      }
      G4[g0*32+f4]=silu4(tof4(a0)); G4[g1*32+f4]=silu4(tof4(a1));
      G4[g2v*32+f4]=silu4(tof4(a2)); G4[g3*32+f4]=silu4(tof4(a3));
      if(v4) G4[g4v*32+f4]=silu4(tof4(a4));
    }
    GBAR();
    // F1 := [silu(gate); from_grid @ G2] (FFMA2)
    {
      int r0=rg8, r1=rg8+8, r2=rg8+16;
      const ulonglong2* G4=(const ulonglong2*)sG2;
      ulonglong2 a0=ZP2,a1=ZP2,a2=ZP2,a3=ZP2;
      #pragma unroll 6
      for(int g=0;g<36;g++){
        ulonglong2 gv=G4[g*32+f4];
        if(rg8>0){ u64 s0=bc2(sFG[r0*36+g]); FMAP(a0,gv,s0); }
        u64 s1=bc2(sFG[r1*36+g]), s2=bc2(sFG[r2*36+g]);
        FMAP(a1,gv,s1); FMAP(a2,gv,s2);
        if(rg8==0){ u64 s3=bc2(sFG[24*36+g]); FMAP(a3,gv,s3); }
      }
      if(rg8==0) a0=tou2(silu4(((const float4*)sGate)[f4]));
      ulonglong2* F2v=(ulonglong2*)sF1;
      F2v[r0*32+f4]=a0; F2v[r1*32+f4]=a1; F2v[r2*32+f4]=a2;
      if(rg8==0) F2v[24*32+f4]=a3;
    }
    GBAR();
    // out = XN + F1 @ ffn_w2 (+b2 row0) (FFMA2)
    {
      int r0=rg, r1=rg+16; bool v1=(r1<25);
      const ulonglong2* w4=(const ulonglong2*)sW2;
      ulonglong2 a0=tou2(((const float4*)sXN)[r0*16+c4]);
      ulonglong2 a1=tou2(v1? ((const float4*)sXN)[r1*16+c4] : Z4);
      if(r0==0){
        ulonglong2 b=tou2(((const float4*)sB2)[c4]);
        padd(a0.x,b.x); padd(a0.y,b.y);
      }
      #pragma unroll 8
      for(int f=0;f<128;f++){
        ulonglong2 wv=w4[f*16+c4];
        u64 s0=bc2(sF1[r0*128+f]); FMAP(a0,wv,s0);
        if(v1){ u64 s1=bc2(sF1[r1*128+f]); FMAP(a1,wv,s1); }
      }
      ulonglong2* op=(ulonglong2*)(out+(size_t)n*1600);
      op[r0*16+c4]=a0;
      if(v1) op[r1*16+c4]=a1;
    }
    GBAR();
  }
}

extern "C" void kernel_launch(void* const* d_in, const int* in_sizes, int n_in,
                              void* d_out, int out_size) {
  const float* x    = (const float*)d_in[0];
  const int*   ei   = (const int*)d_in[1];
  const int*   zn   = (const int*)d_in[2];
  const float* ed   = (const float*)d_in[3];
  const float* wigr = (const float*)d_in[4];
  const float* stab = (const float*)d_in[5];
  const float* ttab = (const float*)d_in[6];
  const float* rw1  = (const float*)d_in[7];
  const float* rb1  = (const float*)d_in[8];
  const float* rw2  = (const float*)d_in[9];
  const float* rb2  = (const float*)d_in[10];
  const float* rw3  = (const float*)d_in[11];
  const float* rb3  = (const float*)d_in[12];
  const float* W1   = (const float*)d_in[13];
  const float* W0e  = (const float*)d_in[14];
  const float* adot = (const float*)d_in[15];
  const float* tg   = (const float*)d_in[16];
  const float* fg   = (const float*)d_in[17];
  const float* po   = (const float*)d_in[18];
  const float* gm1  = (const float*)d_in[19];
  const float* gm2  = (const float*)d_in[20];
  const float* glw  = (const float*)d_in[21];
  const float* glb  = (const float*)d_in[22];
  const float* fw1  = (const float*)d_in[23];
  const float* fb1  = (const float*)d_in[24];
  const float* fw2  = (const float*)d_in[25];
  const float* fb2  = (const float*)d_in[26];
  float* out = (float*)d_out;

  void *pcnt;
  cudaGetSymbolAddress(&pcnt, g_cnt);
  cudaMemsetAsync(pcnt, 0, NN*sizeof(int));

  const int RAD_SMEM  = 52864*4;
  const int EDGE_SMEM = (8192+24576+900+900+128 + 2*EPG)*4;
  const int NODE_SMEM = (30856 + 2*NPG)*4;
  cudaFuncSetAttribute(k_rad,  cudaFuncAttributeMaxDynamicSharedMemorySize, RAD_SMEM);
  cudaFuncSetAttribute(k_edge, cudaFuncAttributeMaxDynamicSharedMemorySize, EDGE_SMEM);
  cudaFuncSetAttribute(k_node, cudaFuncAttributeMaxDynamicSharedMemorySize, NODE_SMEM);

  k_rms1<<<(NN+3)/4, dim3(64,4)>>>(x, gm1);
  k_count<<<(EE+255)/256, 256>>>(ei);
  k_scan<<<1, 1024>>>();
  k_fill<<<(EE+255)/256, 256>>>(ei);
  k_rad<<<296, 256, RAD_SMEM>>>(ed, ei, zn, stab, ttab, rw1, rb1, rw2, rb2, rw3, rb3);
  k_edge<<<148, 512, EDGE_SMEM>>>(wigr, ei, W1, W0e, adot, tg, fg);
  k_node<<<148, 512, NODE_SMEM>>>(x, out, po, gm2, glw, glb, fw1, fb1, fw2, fb2, tg, fg);
}

// round 11
// speedup vs baseline: 1.0787x; 1.0787x over previous
#include <cuda_runtime.h>

#define NN 10000
#define EE 50000
#define NC 25
#define EPG 10332
#define NPG 12224

typedef unsigned long long u64;

__constant__ int c_lof[NC] = {0,1,1,1,2,2,2,2,2,3,3,3,3,3,3,3,4,4,4,4,4,4,4,4,4};

__device__ float    g_h[(size_t)NN*1600];
__device__ float    g_r[(size_t)EE*640];
__device__ float    g_msg[(size_t)EE*1600];
__device__ float    g_alpha[EE*8];
__device__ int      g_cnt[NN];
__device__ int      g_rp[NN+1];
__device__ int      g_cur[NN];
__device__ int      g_ce[EE];

__device__ __forceinline__ float silu(float x){ return x/(1.f+__expf(-x)); }
__device__ __forceinline__ float4 silu4(float4 v){
  return make_float4(silu(v.x),silu(v.y),silu(v.z),silu(v.w));
}
// ---- packed f32x2 helpers ----
__device__ __forceinline__ u64 bc2(float s){
  unsigned i=__float_as_uint(s); u64 r;
  asm("mov.b64 %0,{%1,%1};" : "=l"(r) : "r"(i)); return r;
}
__device__ __forceinline__ void f2(u64&a, u64 v, u64 s){
  asm("fma.rn.f32x2 %0,%1,%2,%0;" : "+l"(a) : "l"(v), "l"(s));
}
__device__ __forceinline__ void m2(u64&a, u64 v){
  asm("mul.rn.f32x2 %0,%0,%1;" : "+l"(a) : "l"(v));
}
__device__ __forceinline__ void padd(u64&a, u64 b){
  asm("add.rn.f32x2 %0,%0,%1;" : "+l"(a) : "l"(b));
}
union F4U { float4 f; ulonglong2 u; };
__device__ __forceinline__ float4 tof4(ulonglong2 a){ F4U u; u.u=a; return u.f; }
__device__ __forceinline__ ulonglong2 tou2(float4 f){ F4U u; u.f=f; return u.u; }
// ---- tf32 mma helpers ----
__device__ __forceinline__ unsigned cvt_tf32(float f){
  unsigned u; asm("cvt.rna.tf32.f32 %0,%1;" : "=r"(u) : "f"(f)); return u;
}
__device__ __forceinline__ void mma_tf32(float&c0,float&c1,float&c2,float&c3,
                                         unsigned a0,unsigned a1,unsigned a2,unsigned a3,
                                         unsigned b0,unsigned b1){
  asm("mma.sync.aligned.m16n8k8.row.col.f32.tf32.tf32.f32 "
      "{%0,%1,%2,%3},{%4,%5,%6,%7},{%8,%9},{%0,%1,%2,%3};"
      : "+f"(c0),"+f"(c1),"+f"(c2),"+f"(c3)
      : "r"(a0),"r"(a1),"r"(a2),"r"(a3),"r"(b0),"r"(b1));
}
#define FMAP(a,v,s) { f2((a).x,(v).x,(s)); f2((a).y,(v).y,(s)); }
#define FMA4(a,s,v) { (a).x=fmaf((s),(v).x,(a).x); (a).y=fmaf((s),(v).y,(a).y); \
                      (a).z=fmaf((s),(v).z,(a).z); (a).w=fmaf((s),(v).w,(a).w); }
#define MUL4(a,v)   { (a).x*=(v).x; (a).y*=(v).y; (a).z*=(v).z; (a).w*=(v).w; }
#define Z4 make_float4(0.f,0.f,0.f,0.f)
#define ZP2 {0ull,0ull}
#define GBAR() asm volatile("bar.sync %0, %1;" :: "r"(grp+1), "r"(256) : "memory")

// ---------------- rmsnorm1 ----------------
__global__ void k_rms1(const float* __restrict__ x, const float* __restrict__ gamma){
  int n = blockIdx.x*4 + threadIdx.y;
  if(n >= NN) return;
  int c = threadIdx.x;
  const float* xp = x + (size_t)n*1600 + c;
  float s = 0.f;
  #pragma unroll
  for(int i=0;i<NC;i++){ float v = xp[i*64]; s += v*v; }
  float gm = rsqrtf(s*(1.f/25.f) + 1e-6f) * gamma[c];
  float* hp = g_h + (size_t)n*1600 + c;
  #pragma unroll
  for(int i=0;i<NC;i++) hp[i*64] = xp[i*64]*gm;
}

// ---------------- CSR build ----------------
__global__ void k_count(const int* __restrict__ ei){
  int e = blockIdx.x*256 + threadIdx.x;
  if(e < EE) atomicAdd(&g_cnt[ei[EE+e]], 1);
}
__global__ void k_scan(){
  __shared__ int ps[1024];
  int t = threadIdx.x;
  int v[10]; int s = 0;
  #pragma unroll
  for(int m=0;m<10;m++){ int i=t*10+m; int c=(i<NN)? g_cnt[i]:0; v[m]=s; s+=c; }
  ps[t]=s; __syncthreads();
  for(int off=1; off<1024; off<<=1){
    int val=(t>=off)? ps[t-off]:0; __syncthreads();
    ps[t]+=val; __syncthreads();
  }
  int excl=(t>0)? ps[t-1]:0;
  #pragma unroll
  for(int m=0;m<10;m++){
    int i=t*10+m;
    if(i<NN){ int o=excl+v[m]; g_rp[i]=o; g_cur[i]=o; }
  }
  if(t==0) g_rp[NN]=EE;
}
__global__ void k_fill(const int* __restrict__ ei){
  int e = blockIdx.x*256 + threadIdx.x;
  if(e < EE) g_ce[atomicAdd(&g_cur[ei[EE+e]],1)] = e;
}

// ---------------- radial MLP ----------------
__global__ __launch_bounds__(256,1)
void k_rad(const float* __restrict__ ed, const int* __restrict__ ei,
           const int* __restrict__ zn,
           const float* __restrict__ st, const float* __restrict__ tt,
           const float* __restrict__ w1, const float* __restrict__ b1,
           const float* __restrict__ w2, const float* __restrict__ b2,
           const float* __restrict__ w3, const float* __restrict__ b3)
{
  extern __shared__ float sm[];
  float* sw1=sm; float* sw2=sw1+6144; float* sw3=sw2+4096;
  float* sb1=sw3+40960; float* sb2=sb1+64; float* sb3=sb2+64;
  float* ef=sb3+640; float* h1=ef+384; float* h2=h1+256;
  int tid=threadIdx.x;
  for(int i=tid;i<6144;i+=256)  sw1[i]=w1[i];
  for(int i=tid;i<4096;i+=256)  sw2[i]=w2[i];
  for(int i=tid;i<40960;i+=256) sw3[i]=w3[i];
  if(tid<64){ sb1[tid]=b1[tid]; sb2[tid]=b2[tid]; }
  for(int i=tid;i<640;i+=256)   sb3[i]=b3[i];
  __syncthreads();

  int grp=tid>>6, t=tid&63;
  int q=grp;
  int nm=(q<2)?3:2;
  int m0=q, m1=q+4, m2=q+8;

  int iters=(EE+(int)gridDim.x*4-1)/((int)gridDim.x*4);
  for(int it=0; it<iters; it++){
    int e0=(it*(int)gridDim.x+(int)blockIdx.x)*4;
    int e=e0+grp;
    bool valid=(e<EE);
    if(t<32){
      if(valid){
        int src=ei[e], dst=ei[EE+e];
        ef[grp*96+t]   =ed[(size_t)e*32+t];
        ef[grp*96+32+t]=st[zn[src]*32+t];
        ef[grp*96+64+t]=tt[zn[dst]*32+t];
      } else {
        ef[grp*96+t]=0.f; ef[grp*96+32+t]=0.f; ef[grp*96+64+t]=0.f;
      }
    }
    __syncthreads();
    {
      float acc=sb1[t];
      const float4* ef4=(const float4*)(ef+grp*96);
      #pragma unroll
      for(int k4=0;k4<24;k4++){
        float4 v=ef4[k4];
        acc=fmaf(v.x,sw1[(k4*4+0)*64+t],acc);
        acc=fmaf(v.y,sw1[(k4*4+1)*64+t],acc);
        acc=fmaf(v.z,sw1[(k4*4+2)*64+t],acc);
        acc=fmaf(v.w,sw1[(k4*4+3)*64+t],acc);
      }
      h1[grp*64+t]=silu(acc);
    }
    __syncthreads();
    {
      float acc=sb2[t];
      const float4* h14=(const float4*)(h1+grp*64);
      #pragma unroll
      for(int k4=0;k4<16;k4++){
        float4 v=h14[k4];
        acc=fmaf(v.x,sw2[(k4*4+0)*64+t],acc);
        acc=fmaf(v.y,sw2[(k4*4+1)*64+t],acc);
        acc=fmaf(v.z,sw2[(k4*4+2)*64+t],acc);
        acc=fmaf(v.w,sw2[(k4*4+3)*64+t],acc);
      }
      h2[grp*64+t]=silu(acc);
    }
    __syncthreads();
    {
      float a0[4], a1[4], a2[4];
      #pragma unroll
      for(int ee=0;ee<4;ee++){ a0[ee]=sb3[t+64*m0]; a1[ee]=sb3[t+64*m1]; a2[ee]=(nm==3)?sb3[t+64*m2]:0.f; }
      for(int k=0;k<64;k++){
        float hh0=h2[k], hh1=h2[64+k], hh2v=h2[128+k], hh3=h2[192+k];
        float wA=sw3[k*640+t+64*m0];
        float wB=sw3[k*640+t+64*m1];
        a0[0]=fmaf(wA,hh0,a0[0]); a0[1]=fmaf(wA,hh1,a0[1]); a0[2]=fmaf(wA,hh2v,a0[2]); a0[3]=fmaf(wA,hh3,a0[3]);
        a1[0]=fmaf(wB,hh0,a1[0]); a1[1]=fmaf(wB,hh1,a1[1]); a1[2]=fmaf(wB,hh2v,a1[2]); a1[3]=fmaf(wB,hh3,a1[3]);
        if(nm==3){
          float wC=sw3[k*640+t+64*m2];
          a2[0]=fmaf(wC,hh0,a2[0]); a2[1]=fmaf(wC,hh1,a2[1]); a2[2]=fmaf(wC,hh2v,a2[2]); a2[3]=fmaf(wC,hh3,a2[3]);
        }
      }
      #pragma unroll
      for(int ee=0;ee<4;ee++){
        int eo=e0+ee;
        if(eo<EE){
          g_r[(size_t)eo*640+t+64*m0]=a0[ee];
          g_r[(size_t)eo*640+t+64*m1]=a1[ee];
          if(nm==3) g_r[(size_t)eo*640+t+64*m2]=a2[ee];
        }
      }
    }
    __syncthreads();
  }
}

// ---------------- per-edge kernel: prefetch pipeline + tf32 mma msg ----------------
__global__ __launch_bounds__(512,1)
void k_edge(const float* __restrict__ wigner, const int* __restrict__ ei,
            const float* __restrict__ W1, const float* __restrict__ W0,
            const float* __restrict__ adot, const float* __restrict__ tg,
            const float* __restrict__ fg)
{
  extern __shared__ float sm[];
  unsigned* sW1p = (unsigned*)sm; // 128*72 tf32 bits = 9216
  float* sW0 = sm+9216;     // 24576 transposed
  float* sTG = sW0+24576;   // 900
  float* sFG = sTG+900;     // 900
  float* sAD = sFG+900;     // 128
  float* pe  = sAD+128;     // 2 * EPG
  int tid=threadIdx.x;
  for(int i=tid;i<8192;i+=512){ int c=i>>6,h=i&63; sW1p[c*72+h]=cvt_tf32(W1[i]); }
  for(int i=tid;i<24576;i+=512){ int o=i>>7,c=i&127; sW0[i]=W0[c*192+o]; }
  for(int i=tid;i<900;i+=512){ sTG[i]=tg[i]; sFG[i]=fg[i]; }
  if(tid<128) sAD[tid]=adot[tid];
  __syncthreads();

  int grp = tid>>8, t = tid&255;
  float* base  = pe + grp*EPG;
  float* swigA = base;          // 700
  float* swigB = base+700;      // 700
  float* scat  = base+1400;     // 3200
  float* srr   = base+4600;     // 640
  float* sxe   = base+5240;     // 3300 (25 rows x stride 132)
  float* sextra= base+8540;     // 192
  float* smsg  = base+8732;     // 1600 (aliased as smact)
  float* sgrid = sxe;           // reuse after msg consumed... careful: grid written after msg read
  float* smact = smsg;

  int c4=t&31, rg8=t>>5;
  int h4=t&15, rg16=t>>4;

  int stride = (int)gridDim.x*2;
  int e = (int)blockIdx.x*2 + grp;
  int p = 0;

  {
    const float* wp=wigner+(size_t)e*625;
    for(int i=t;i<625;i+=256) swigA[(i/25)*28+(i%25)]=wp[i];
    int src=ei[e], dst=ei[EE+e];
    const float4* hs=(const float4*)(g_h+(size_t)src*1600);
    const float4* hd=(const float4*)(g_h+(size_t)dst*1600);
    float4* cat4=(float4*)scat;
    for(int i=t;i<800;i+=256){ int j=i>>5,qq=i&31; cat4[i]=(qq<16)?hs[j*16+qq]:hd[j*16+qq-16]; }
    const float4* rp4=(const float4*)(g_r+(size_t)e*640);
    float4* srr4=(float4*)srr;
    for(int i=t;i<160;i+=256) srr4[i]=rp4[i];
  }

  for(; e<EE; e+=stride){
    int en = e + stride; if(en >= EE) en = e;
    float* swig  = p? swigB : swigA;
    float* swigN = p? swigA : swigB;
    GBAR();

    // xe = (wig @ cat) * r[EXPAND]  (FFMA2, stride-132 rows)
    {
      const ulonglong2* catp=(const ulonglong2*)scat;
      const ulonglong2* r4=(const ulonglong2*)srr;
      ulonglong2* xe2=(ulonglong2*)sxe;
      int r0=rg8, r1=rg8+8, r2=rg8+16;
      ulonglong2 a0=ZP2,a1=ZP2,a2=ZP2,a3=ZP2;
      #pragma unroll
      for(int j4=0;j4<6;j4++){
        float4 w0=*(const float4*)&swig[r0*28+j4*4];
        float4 w1v=*(const float4*)&swig[r1*28+j4*4];
        float4 w2v=*(const float4*)&swig[r2*28+j4*4];
        float4 w3v=*(const float4*)&swig[24*28+j4*4];
        #pragma unroll
        for(int tt2=0;tt2<4;tt2++){
          ulonglong2 cv=catp[(j4*4+tt2)*32+c4];
          u64 s0=bc2(((const float*)&w0)[tt2]);
          u64 s1=bc2(((const float*)&w1v)[tt2]);
          u64 s2=bc2(((const float*)&w2v)[tt2]);
          FMAP(a0,cv,s0); FMAP(a1,cv,s1); FMAP(a2,cv,s2);
          if(rg8==0){ u64 s3=bc2(((const float*)&w3v)[tt2]); FMAP(a3,cv,s3); }
        }
      }
      { ulonglong2 cv=catp[24*32+c4];
        u64 s0=bc2(swig[r0*28+24]), s1=bc2(swig[r1*28+24]), s2=bc2(swig[r2*28+24]);
        FMAP(a0,cv,s0); FMAP(a1,cv,s1); FMAP(a2,cv,s2);
        if(rg8==0){ u64 s3=bc2(swig[24*28+24]); FMAP(a3,cv,s3); }
      }
      ulonglong2 rv;
      rv=r4[c_lof[r0]*32+c4]; m2(a0.x,rv.x); m2(a0.y,rv.y); xe2[r0*33+c4]=a0;
      rv=r4[c_lof[r1]*32+c4]; m2(a1.x,rv.x); m2(a1.y,rv.y); xe2[r1*33+c4]=a1;
      rv=r4[c_lof[r2]*32+c4]; m2(a2.x,rv.x); m2(a2.y,rv.y); xe2[r2*33+c4]=a2;
      if(rg8==0){ rv=r4[4*32+c4]; m2(a3.x,rv.x); m2(a3.y,rv.y); xe2[24*33+c4]=a3; }
    }
    GBAR();

    // prefetch next edge
    {
      const float* wp=wigner+(size_t)en*625;
      for(int i=t;i<625;i+=256) swigN[(i/25)*28+(i%25)]=wp[i];
      int nsrc=ei[en], ndst=ei[EE+en];
      const float4* hs=(const float4*)(g_h+(size_t)nsrc*1600);
      const float4* hd=(const float4*)(g_h+(size_t)ndst*1600);
      float4* cat4=(float4*)scat;
      for(int i=t;i<800;i+=256){ int j=i>>5,qq=i&31; cat4[i]=(qq<16)?hs[j*16+qq]:hd[j*16+qq-16]; }
      const float4* rp4=(const float4*)(g_r+(size_t)en*640);
      float4* srr4=(float4*)srr;
      for(int i=t;i<160;i+=256) srr4[i]=rp4[i];
    }

    // msg = xe @ W1 via tf32 mma (m16n8k8), + extra by all threads after
    {
      int w=t>>5, lane=t&31;
      int mt=w>>2, nq=w&3;
      int r=lane>>2, cq=lane&3;
      int rowA=mt*16+r;
      const float* A0=sxe+rowA*132;
      const float* A1=sxe+(rowA+8)*132;
      float acc[2][4]={{0.f,0.f,0.f,0.f},{0.f,0.f,0.f,0.f}};
      #pragma unroll
      for(int kc=0;kc<16;kc++){
        int k0=kc*8;
        unsigned a0=cvt_tf32(A0[k0+cq]);
        unsigned a1=cvt_tf32(A1[k0+cq]);
        unsigned a2=cvt_tf32(A0[k0+cq+4]);
        unsigned a3=cvt_tf32(A1[k0+cq+4]);
        #pragma unroll
        for(int nt=0;nt<2;nt++){
          int nb=nq*16+nt*8;
          unsigned b0=sW1p[(k0+cq)*72+nb+r];
          unsigned b1=sW1p[(k0+cq+4)*72+nb+r];
          mma_tf32(acc[nt][0],acc[nt][1],acc[nt][2],acc[nt][3],a0,a1,a2,a3,b0,b1);
        }
      }
      int row0=mt*16+r, row1=row0+8;
      #pragma unroll
      for(int nt=0;nt<2;nt++){
        int col=nq*16+nt*8+2*cq;
        if(row0<25){ smsg[row0*64+col]=acc[nt][0]; smsg[row0*64+col+1]=acc[nt][1]; }
        if(row1<25){ smsg[row1*64+col]=acc[nt][2]; smsg[row1*64+col+1]=acc[nt][3]; }
      }
    }
    if(t<192){
      const float4* x0=(const float4*)sxe;  // row 0 (stride irrelevant)
      const float4* w=(const float4*)(sW0+t*128);
      float4 acc=Z4;
      #pragma unroll 8
      for(int k=0;k<32;k++){ float4 xv=x0[k], wv=w[k];
        acc.x=fmaf(xv.x,wv.x,acc.x); acc.y=fmaf(xv.y,wv.y,acc.y);
        acc.z=fmaf(xv.z,wv.z,acc.z); acc.w=fmaf(xv.w,wv.w,acc.w); }
      sextra[t]=acc.x+acc.y+acc.z+acc.w;
    }
    GBAR();

    // grid = silu(to_grid @ msg) (FFMA2)  + alpha by t<8
    if(t<8){
      float acc=0.f;
      #pragma unroll
      for(int a=0;a<16;a++){ float v=sextra[t*16+a]; acc=fmaf(silu(v),sAD[t*16+a],acc); }
      g_alpha[e*8+t]=acc;
    }
    {
      int g0=rg16, g1=rg16+16, g2v=rg16+32; bool v2=(g2v<36);
      const ulonglong2* m4=(const ulonglong2*)smsg;
      float4* gr4=(float4*)sgrid;
      ulonglong2 a0=ZP2,a1=ZP2,a2=ZP2;
      #pragma unroll
      for(int i=0;i<25;i++){
        ulonglong2 mv=m4[i*16+h4];
        u64 s0=bc2(sTG[g0*25+i]), s1=bc2(sTG[g1*25+i]);
        FMAP(a0,mv,s0); FMAP(a1,mv,s1);
        if(v2){ u64 s2=bc2(sTG[g2v*25+i]); FMAP(a2,mv,s2); }
      }
      gr4[g0*16+h4]=silu4(tof4(a0));
      gr4[g1*16+h4]=silu4(tof4(a1));
      if(v2) gr4[g2v*16+h4]=silu4(tof4(a2));
    }
    GBAR();

    // mact = [silu(gate); from_grid @ grid] (FFMA2)
    {
      int r0=rg16, r1=rg16+16; bool v1=(r1<25);
      const ulonglong2* gr4=(const ulonglong2*)sgrid;
      ulonglong2 a0=ZP2,a1=ZP2;
      #pragma unroll 6
      for(int g=0;g<36;g++){
        ulonglong2 gv=gr4[g*16+h4];
        if(rg16>0){ u64 s0=bc2(sFG[r0*36+g]); FMAP(a0,gv,s0); }
        if(v1){ u64 s1=bc2(sFG[r1*36+g]); FMAP(a1,gv,s1); }
      }
      if(rg16==0) a0=tou2(silu4(((const float4*)(sextra+128))[h4]));
      ((ulonglong2*)smact)[r0*16+h4]=a0;
      if(v1) ((ulonglong2*)smact)[r1*16+h4]=a1;
    }
    GBAR();

    // rotated = wig^T @ mact (FFMA2) -> global
    {
      int r0=rg16, r1=rg16+16; bool v1=(r1<25);
      const ulonglong2* m4=(const ulonglong2*)smact;
      ulonglong2 a0=ZP2,a1=ZP2;
      #pragma unroll
      for(int j=0;j<25;j++){
        ulonglong2 mv=m4[j*16+h4];
        u64 s0=bc2(swig[j*28+r0]); FMAP(a0,mv,s0);
        if(v1){ u64 s1=bc2(swig[j*28+r1]); FMAP(a1,mv,s1); }
      }
      ulonglong2* op=(ulonglong2*)(g_msg+(size_t)e*1600);
      op[r0*16+h4]=a0;
      if(v1) op[r1*16+h4]=a1;
    }
    p ^= 1;
  }
}

// ---------------- node: fused softmax + gather + proj + rmsnorm2 + FFN ----------------
__global__ __launch_bounds__(512,1)
void k_node(const float* __restrict__ x, float* __restrict__ out,
            const float* __restrict__ po, const float* __restrict__ g2w,
            const float* __restrict__ glw, const float* __restrict__ glb,
            const float* __restrict__ fw1, const float* __restrict__ fb1,
            const float* __restrict__ fw2, const float* __restrict__ fb2,
            const float* __restrict__ tg, const float* __restrict__ fg)
{
  extern __shared__ float sm[];
  float* sPO  = sm;           // 4096
  float* sGL  = sPO+4096;     // 8192
  float* sW1f = sGL+8192;     // 8192
  float* sW2  = sW1f+8192;    // 8192
  float* sTG  = sW2+8192;     // 900
  float* sFG  = sTG+900;      // 900
  float* sGLB = sFG+900;      // 128
  float* sB1  = sGLB+128;     // 128
  float* sB2  = sB1+128;      // 64
  float* sGam = sB2+64;       // 64
  float* pn   = sGam+64;      // 2 * NPG
  int tid=threadIdx.x;
  for(int i=tid;i<4096;i+=512) sPO[i]=po[i];
  for(int i=tid;i<8192;i+=512){ sGL[i]=glw[i]; sW1f[i]=fw1[i]; sW2[i]=fw2[i]; }
  for(int i=tid;i<900;i+=512){ sTG[i]=tg[i]; sFG[i]=fg[i]; }
  if(tid<128){ sGLB[tid]=glb[tid]; sB1[tid]=fb1[tid]; }
  if(tid<64){ sB2[tid]=fb2[tid]; sGam[tid]=g2w[tid]; }
  __syncthreads();

  int grp=tid>>8, t=tid&255;
  float* base = pn + grp*NPG;
  float* sCE  = base;
  float* sAL  = base+64;
  float* sEW  = base+576;
  float* sXN  = base+1088;
  float* sH   = sXN+1600;
  float* sGate= sH+1600;
  float* sF1  = sGate+128;
  float* sG2  = sF1+3200;
  float* sA   = sG2;
  int* sCEi = (int*)sCE;

  int c4=t&15, rg=t>>4;
  int f4=t&31, rg8=t>>5;

  for(int nb=blockIdx.x*2; nb<NN; nb+=gridDim.x*2){
    int n = nb + grp;
    int beg=g_rp[n], end=g_rp[n+1];
    int deg=end-beg;
    float4* sA4=(float4*)sA;
    for(int i=t;i<400;i+=256) sA4[i]=Z4;
    if(t<16) sGate[t] = (t<8)? -3.0e38f : 0.f;
    GBAR();

    for(int k0=beg; k0<end; k0+=64){
      int kc=min(64,end-k0);
      for(int idx=t; idx<kc; idx+=256) sCEi[idx]=g_ce[k0+idx];
      GBAR();
      for(int idx=t; idx<kc*2; idx+=256){
        int j=idx>>1, q=idx&1;
        ((float4*)sAL)[j*2+q] = ((const float4*)(g_alpha+(size_t)sCEi[j]*8))[q];
      }
      GBAR();
      if(t<8){
        float m=sGate[t], s=sGate[8+t];
        for(int j=0;j<kc;j++){
          float a=sAL[j*8+t];
          if(a>m){ s=s*__expf(m-a)+1.f; m=a; }
          else    s+=__expf(a-m);
        }
        sGate[t]=m; sGate[8+t]=s;
      }
      GBAR();
    }
    if(t<8) sGate[8+t]=1.f/(sGate[8+t]+1e-8f);
    GBAR();

    for(int k0=beg; k0<end; k0+=64){
      int kc=min(64,end-k0);
      if(deg>64){
        for(int idx=t; idx<kc; idx+=256) sCEi[idx]=g_ce[k0+idx];
        GBAR();
        for(int idx=t; idx<kc*2; idx+=256){
          int j=idx>>1, q=idx&1;
          ((float4*)sAL)[j*2+q] = ((const float4*)(g_alpha+(size_t)sCEi[j]*8))[q];
        }
      }
      GBAR();
      for(int idx=t; idx<kc*8; idx+=256)
        sEW[idx]=__expf(sAL[idx]-sGate[idx&7])*sGate[8+(idx&7)];
      GBAR();
      for(int j=0;j<kc;j++){
        int e=sCEi[j];
        const float4* mp=(const float4*)(g_msg+(size_t)e*1600);
        const float* wj = sEW + j*8;
        for(int i=t;i<400;i+=256){
          float w=wj[(i&15)>>1];
          float4 v=mp[i];
          float4 a=sA4[i];
          FMA4(a,w,v);
          sA4[i]=a;
        }
      }
      GBAR();
    }

    // XN = x + agg @ proj_out (FFMA2)
    {
      int r0=rg, r1=rg+16; bool v1=(r1<25);
      const float4* x4g=(const float4*)(x+(size_t)n*1600);
      const ulonglong2* p4=(const ulonglong2*)sPO;
      ulonglong2 a0=tou2(x4g[r0*16+c4]);
      ulonglong2 a1=tou2(v1? x4g[r1*16+c4] : Z4);
      #pragma unroll 8
      for(int k=0;k<64;k++){
        ulonglong2 wv=p4[k*16+c4];
        u64 s0=bc2(sA[r0*64+k]); FMAP(a0,wv,s0);
        if(v1){ u64 s1=bc2(sA[r1*64+k]); FMAP(a1,wv,s1); }
      }
      ((ulonglong2*)sXN)[r0*16+c4]=a0;
      if(v1) ((ulonglong2*)sXN)[r1*16+c4]=a1;
    }
    GBAR();
    if(t<64){
      float s=0.f;
      #pragma unroll
      for(int i=0;i<NC;i++){ float v=sXN[i*64+t]; s=fmaf(v,v,s); }
      sGate[t]=rsqrtf(s*(1.f/25.f)+1e-6f)*sGam[t];
    }
    GBAR();
    {
      float4* sH4=(float4*)sH;
      const float4* xn4=(const float4*)sXN;
      const float4* rv4=(const float4*)sGate;
      for(int i=t;i<400;i+=256){ float4 v=xn4[i], r=rv4[i&15]; MUL4(v,r); sH4[i]=v; }
    }
    GBAR();
    float gacc=0.f;
    if(t<128){
      gacc=sGLB[t];
      #pragma unroll 8
      for(int c=0;c<64;c++) gacc=fmaf(sH[c],sGL[c*128+t],gacc);
    }
    GBAR();
    if(t<128) sGate[t]=gacc;
    // F1 = h @ ffn_w1 (+b1 row0) (FFMA2)
    {
      int r0=rg8, r1=rg8+8, r2=rg8+16;
      const ulonglong2* w4=(const ulonglong2*)sW1f;
      ulonglong2 a0=ZP2,a1=ZP2,a2=ZP2,a3=ZP2;
      #pragma unroll 8
      for(int c=0;c<64;c++){
        ulonglong2 wv=w4[c*32+f4];
        u64 s0=bc2(sH[r0*64+c]), s1=bc2(sH[r1*64+c]), s2=bc2(sH[r2*64+c]);
        FMAP(a0,wv,s0); FMAP(a1,wv,s1); FMAP(a2,wv,s2);
        if(rg8==0){ u64 s3=bc2(sH[24*64+c]); FMAP(a3,wv,s3); }
      }
      if(rg8==0){
        ulonglong2 b=tou2(((const float4*)sB1)[f4]);
        padd(a0.x,b.x); padd(a0.y,b.y);
      }
      ulonglong2* F2v=(ulonglong2*)sF1;
      F2v[r0*32+f4]=a0; F2v[r1*32+f4]=a1; F2v[r2*32+f4]=a2;
      if(rg8==0) F2v[24*32+f4]=a3;
    }
    GBAR();
    // G2 = silu(to_grid @ F1) (FFMA2)
    {
      int g0=rg8, g1=rg8+8, g2v=rg8+16, g3=rg8+24, g4v=rg8+32; bool v4=(g4v<36);
      const ulonglong2* F4p=(const ulonglong2*)sF1;
      float4* G4=(float4*)sG2;
      ulonglong2 a0=ZP2,a1=ZP2,a2=ZP2,a3=ZP2,a4=ZP2;
      #pragma unroll
      for(int i=0;i<25;i++){
        ulonglong2 fv=F4p[i*32+f4];
        u64 s0=bc2(sTG[g0*25+i]), s1=bc2(sTG[g1*25+i]);
        u64 s2=bc2(sTG[g2v*25+i]), s3=bc2(sTG[g3*25+i]);
        FMAP(a0,fv,s0); FMAP(a1,fv,s1); FMAP(a2,fv,s2); FMAP(a3,fv,s3);
        if(v4){ u64 s4=bc2(sTG[g4v*25+i]); FMAP(a4,fv,s4); }
      }
      G4[g0*32+f4]=silu4(tof4(a0)); G4[g1*32+f4]=silu4(tof4(a1));
      G4[g2v*32+f4]=silu4(tof4(a2)); G4[g3*32+f4]=silu4(tof4(a3));
      if(v4) G4[g4v*32+f4]=silu4(tof4(a4));
    }
    GBAR();
    // F1 := [silu(gate); from_grid @ G2] (FFMA2)
    {
      int r0=rg8, r1=rg8+8, r2=rg8+16;
      const ulonglong2* G4=(const ulonglong2*)sG2;
      ulonglong2 a0=ZP2,a1=ZP2,a2=ZP2,a3=ZP2;
      #pragma unroll 6
      for(int g=0;g<36;g++){
        ulonglong2 gv=G4[g*32+f4];
        if(rg8>0){ u64 s0=bc2(sFG[r0*36+g]); FMAP(a0,gv,s0); }
        u64 s1=bc2(sFG[r1*36+g]), s2=bc2(sFG[r2*36+g]);
        FMAP(a1,gv,s1); FMAP(a2,gv,s2);
        if(rg8==0){ u64 s3=bc2(sFG[24*36+g]); FMAP(a3,gv,s3); }
      }
      if(rg8==0) a0=tou2(silu4(((const float4*)sGate)[f4]));
      ulonglong2* F2v=(ulonglong2*)sF1;
      F2v[r0*32+f4]=a0; F2v[r1*32+f4]=a1; F2v[r2*32+f4]=a2;
      if(rg8==0) F2v[24*32+f4]=a3;
    }
    GBAR();
    // out = XN + F1 @ ffn_w2 (+b2 row0) (FFMA2)
    {
      int r0=rg, r1=rg+16; bool v1=(r1<25);
      const ulonglong2* w4=(const ulonglong2*)sW2;
      ulonglong2 a0=tou2(((const float4*)sXN)[r0*16+c4]);
      ulonglong2 a1=tou2(v1? ((const float4*)sXN)[r1*16+c4] : Z4);
      if(r0==0){
        ulonglong2 b=tou2(((const float4*)sB2)[c4]);
        padd(a0.x,b.x); padd(a0.y,b.y);
      }
      #pragma unroll 8
      for(int f=0;f<128;f++){
        ulonglong2 wv=w4[f*16+c4];
        u64 s0=bc2(sF1[r0*128+f]); FMAP(a0,wv,s0);
        if(v1){ u64 s1=bc2(sF1[r1*128+f]); FMAP(a1,wv,s1); }
      }
      ulonglong2* op=(ulonglong2*)(out+(size_t)n*1600);
      op[r0*16+c4]=a0;
      if(v1) op[r1*16+c4]=a1;
    }
    GBAR();
  }
}

extern "C" void kernel_launch(void* const* d_in, const int* in_sizes, int n_in,
                              void* d_out, int out_size) {
  const float* x    = (const float*)d_in[0];
  const int*   ei   = (const int*)d_in[1];
  const int*   zn   = (const int*)d_in[2];
  const float* ed   = (const float*)d_in[3];
  const float* wigr = (const float*)d_in[4];
  const float* stab = (const float*)d_in[5];
  const float* ttab = (const float*)d_in[6];
  const float* rw1  = (const float*)d_in[7];
  const float* rb1  = (const float*)d_in[8];
  const float* rw2  = (const float*)d_in[9];
  const float* rb2  = (const float*)d_in[10];
  const float* rw3  = (const float*)d_in[11];
  const float* rb3  = (const float*)d_in[12];
  const float* W1   = (const float*)d_in[13];
  const float* W0e  = (const float*)d_in[14];
  const float* adot = (const float*)d_in[15];
  const float* tg   = (const float*)d_in[16];
  const float* fg   = (const float*)d_in[17];
  const float* po   = (const float*)d_in[18];
  const float* gm1  = (const float*)d_in[19];
  const float* gm2  = (const float*)d_in[20];
  const float* glw  = (const float*)d_in[21];
  const float* glb  = (const float*)d_in[22];
  const float* fw1  = (const float*)d_in[23];
  const float* fb1  = (const float*)d_in[24];
  const float* fw2  = (const float*)d_in[25];
  const float* fb2  = (const float*)d_in[26];
  float* out = (float*)d_out;

  void *pcnt;
  cudaGetSymbolAddress(&pcnt, g_cnt);
  cudaMemsetAsync(pcnt, 0, NN*sizeof(int));

  const int RAD_SMEM  = 52864*4;
  const int EDGE_SMEM = (9216+24576+900+900+128 + 2*EPG)*4;   // 225536
  const int NODE_SMEM = (30856 + 2*NPG)*4;
  cudaFuncSetAttribute(k_rad,  cudaFuncAttributeMaxDynamicSharedMemorySize, RAD_SMEM);
  cudaFuncSetAttribute(k_edge, cudaFuncAttributeMaxDynamicSharedMemorySize, EDGE_SMEM);
  cudaFuncSetAttribute(k_node, cudaFuncAttributeMaxDynamicSharedMemorySize, NODE_SMEM);

  k_rms1<<<(NN+3)/4, dim3(64,4)>>>(x, gm1);
  k_count<<<(EE+255)/256, 256>>>(ei);
  k_scan<<<1, 1024>>>();
  k_fill<<<(EE+255)/256, 256>>>(ei);
  k_rad<<<296, 256, RAD_SMEM>>>(ed, ei, zn, stab, ttab, rw1, rb1, rw2, rb2, rw3, rb3);
  k_edge<<<148, 512, EDGE_SMEM>>>(wigr, ei, W1, W0e, adot, tg, fg);
  k_node<<<148, 512, NODE_SMEM>>>(x, out, po, gm2, glw, glb, fw1, fb1, fw2, fb2, tg, fg);
}

// round 14
// speedup vs baseline: 1.1579x; 1.0734x over previous
#include <cuda_runtime.h>

#define NN 10000
#define EE 50000
#define NC 25
#define EPG 11032
#define NPG 12424

typedef unsigned long long u64;

__constant__ int c_lof[NC] = {0,1,1,1,2,2,2,2,2,3,3,3,3,3,3,3,4,4,4,4,4,4,4,4,4};

__device__ float    g_h[(size_t)NN*1600];
__device__ float    g_r[(size_t)EE*640];
__device__ float    g_msg[(size_t)EE*1600];
__device__ float    g_alpha[EE*8];
__device__ int      g_cnt[NN];
__device__ int      g_rp[NN+1];
__device__ int      g_cur[NN];
__device__ int      g_ce[EE];

__device__ __forceinline__ float silu(float x){ return x/(1.f+__expf(-x)); }
__device__ __forceinline__ float4 silu4(float4 v){
  return make_float4(silu(v.x),silu(v.y),silu(v.z),silu(v.w));
}
__device__ __forceinline__ u64 bc2(float s){
  unsigned i=__float_as_uint(s); u64 r;
  asm("mov.b64 %0,{%1,%1};" : "=l"(r) : "r"(i)); return r;
}
__device__ __forceinline__ void f2(u64&a, u64 v, u64 s){
  asm("fma.rn.f32x2 %0,%1,%2,%0;" : "+l"(a) : "l"(v), "l"(s));
}
__device__ __forceinline__ void m2(u64&a, u64 v){
  asm("mul.rn.f32x2 %0,%0,%1;" : "+l"(a) : "l"(v));
}
__device__ __forceinline__ void padd(u64&a, u64 b){
  asm("add.rn.f32x2 %0,%0,%1;" : "+l"(a) : "l"(b));
}
union F4U { float4 f; ulonglong2 u; };
__device__ __forceinline__ float4 tof4(ulonglong2 a){ F4U u; u.u=a; return u.f; }
__device__ __forceinline__ ulonglong2 tou2(float4 f){ F4U u; u.f=f; return u.u; }
__device__ __forceinline__ unsigned cvt_tf32(float f){
  unsigned u; asm("cvt.rna.tf32.f32 %0,%1;" : "=r"(u) : "f"(f)); return u;
}
__device__ __forceinline__ void mma_tf32(float&c0,float&c1,float&c2,float&c3,
                                         unsigned a0,unsigned a1,unsigned a2,unsigned a3,
                                         unsigned b0,unsigned b1){
  asm("mma.sync.aligned.m16n8k8.row.col.f32.tf32.tf32.f32 "
      "{%0,%1,%2,%3},{%4,%5,%6,%7},{%8,%9},{%0,%1,%2,%3};"
      : "+f"(c0),"+f"(c1),"+f"(c2),"+f"(c3)
      : "r"(a0),"r"(a1),"r"(a2),"r"(a3),"r"(b0),"r"(b1));
}
#define FMAP(a,v,s) { f2((a).x,(v).x,(s)); f2((a).y,(v).y,(s)); }
#define FMA4(a,s,v) { (a).x=fmaf((s),(v).x,(a).x); (a).y=fmaf((s),(v).y,(a).y); \
                      (a).z=fmaf((s),(v).z,(a).z); (a).w=fmaf((s),(v).w,(a).w); }
#define MUL4(a,v)   { (a).x*=(v).x; (a).y*=(v).y; (a).z*=(v).z; (a).w*=(v).w; }
#define Z4 make_float4(0.f,0.f,0.f,0.f)
#define ZP2 {0ull,0ull}
#define GBAR() asm volatile("bar.sync %0, %1;" :: "r"(grp+1), "r"(256) : "memory")

// ---------------- rmsnorm1 ----------------
__global__ void k_rms1(const float* __restrict__ x, const float* __restrict__ gamma){
  int n = blockIdx.x*4 + threadIdx.y;
  if(n >= NN) return;
  int c = threadIdx.x;
  const float* xp = x + (size_t)n*1600 + c;
  float s = 0.f;
  #pragma unroll
  for(int i=0;i<NC;i++){ float v = xp[i*64]; s += v*v; }
  float gm = rsqrtf(s*(1.f/25.f) + 1e-6f) * gamma[c];
  float* hp = g_h + (size_t)n*1600 + c;
  #pragma unroll
  for(int i=0;i<NC;i++) hp[i*64] = xp[i*64]*gm;
}

// ---------------- CSR build ----------------
__global__ void k_count(const int* __restrict__ ei){
  int e = blockIdx.x*256 + threadIdx.x;
  if(e < EE) atomicAdd(&g_cnt[ei[EE+e]], 1);
}
__global__ void k_scan(){
  __shared__ int ps[1024];
  int t = threadIdx.x;
  int v[10]; int s = 0;
  #pragma unroll
  for(int m=0;m<10;m++){ int i=t*10+m; int c=(i<NN)? g_cnt[i]:0; v[m]=s; s+=c; }
  ps[t]=s; __syncthreads();
  for(int off=1; off<1024; off<<=1){
    int val=(t>=off)? ps[t-off]:0; __syncthreads();
    ps[t]+=val; __syncthreads();
  }
  int excl=(t>0)? ps[t-1]:0;
  #pragma unroll
  for(int m=0;m<10;m++){
    int i=t*10+m;
    if(i<NN){ int o=excl+v[m]; g_rp[i]=o; g_cur[i]=o; }
  }
  if(t==0) g_rp[NN]=EE;
}
__global__ void k_fill(const int* __restrict__ ei){
  int e = blockIdx.x*256 + threadIdx.x;
  if(e < EE) g_ce[atomicAdd(&g_cur[ei[EE+e]],1)] = e;
}

// ---------------- radial MLP ----------------
__global__ __launch_bounds__(256,1)
void k_rad(const float* __restrict__ ed, const int* __restrict__ ei,
           const int* __restrict__ zn,
           const float* __restrict__ st, const float* __restrict__ tt,
           const float* __restrict__ w1, const float* __restrict__ b1,
           const float* __restrict__ w2, const float* __restrict__ b2,
           const float* __restrict__ w3, const float* __restrict__ b3)
{
  extern __shared__ float sm[];
  float* sw1=sm; float* sw2=sw1+6144; float* sw3=sw2+4096;
  float* sb1=sw3+40960; float* sb2=sb1+64; float* sb3=sb2+64;
  float* ef=sb3+640; float* h1=ef+384; float* h2=h1+256;
  int tid=threadIdx.x;
  for(int i=tid;i<6144;i+=256)  sw1[i]=w1[i];
  for(int i=tid;i<4096;i+=256)  sw2[i]=w2[i];
  for(int i=tid;i<40960;i+=256) sw3[i]=w3[i];
  if(tid<64){ sb1[tid]=b1[tid]; sb2[tid]=b2[tid]; }
  for(int i=tid;i<640;i+=256)   sb3[i]=b3[i];
  __syncthreads();

  int grp=tid>>6, t=tid&63;
  int q=grp;
  int nm=(q<2)?3:2;
  int m0=q, m1=q+4, m2=q+8;

  int iters=(EE+(int)gridDim.x*4-1)/((int)gridDim.x*4);
  for(int it=0; it<iters; it++){
    int e0=(it*(int)gridDim.x+(int)blockIdx.x)*4;
    int e=e0+grp;
    bool valid=(e<EE);
    if(t<32){
      if(valid){
        int src=ei[e], dst=ei[EE+e];
        ef[grp*96+t]   =ed[(size_t)e*32+t];
        ef[grp*96+32+t]=st[zn[src]*32+t];
        ef[grp*96+64+t]=tt[zn[dst]*32+t];
      } else {
        ef[grp*96+t]=0.f; ef[grp*96+32+t]=0.f; ef[grp*96+64+t]=0.f;
      }
    }
    __syncthreads();
    {
      float acc=sb1[t];
      const float4* ef4=(const float4*)(ef+grp*96);
      #pragma unroll
      for(int k4=0;k4<24;k4++){
        float4 v=ef4[k4];
        acc=fmaf(v.x,sw1[(k4*4+0)*64+t],acc);
        acc=fmaf(v.y,sw1[(k4*4+1)*64+t],acc);
        acc=fmaf(v.z,sw1[(k4*4+2)*64+t],acc);
        acc=fmaf(v.w,sw1[(k4*4+3)*64+t],acc);
      }
      h1[grp*64+t]=silu(acc);
    }
    __syncthreads();
    {
      float acc=sb2[t];
      const float4* h14=(const float4*)(h1+grp*64);
      #pragma unroll
      for(int k4=0;k4<16;k4++){
        float4 v=h14[k4];
        acc=fmaf(v.x,sw2[(k4*4+0)*64+t],acc);
        acc=fmaf(v.y,sw2[(k4*4+1)*64+t],acc);
        acc=fmaf(v.z,sw2[(k4*4+2)*64+t],acc);
        acc=fmaf(v.w,sw2[(k4*4+3)*64+t],acc);
      }
      h2[grp*64+t]=silu(acc);
    }
    __syncthreads();
    {
      float a0[4], a1[4], a2[4];
      #pragma unroll
      for(int ee=0;ee<4;ee++){ a0[ee]=sb3[t+64*m0]; a1[ee]=sb3[t+64*m1]; a2[ee]=(nm==3)?sb3[t+64*m2]:0.f; }
      for(int k=0;k<64;k++){
        float hh0=h2[k], hh1=h2[64+k], hh2v=h2[128+k], hh3=h2[192+k];
        float wA=sw3[k*640+t+64*m0];
        float wB=sw3[k*640+t+64*m1];
        a0[0]=fmaf(wA,hh0,a0[0]); a0[1]=fmaf(wA,hh1,a0[1]); a0[2]=fmaf(wA,hh2v,a0[2]); a0[3]=fmaf(wA,hh3,a0[3]);
        a1[0]=fmaf(wB,hh0,a1[0]); a1[1]=fmaf(wB,hh1,a1[1]); a1[2]=fmaf(wB,hh2v,a1[2]); a1[3]=fmaf(wB,hh3,a1[3]);
        if(nm==3){
          float wC=sw3[k*640+t+64*m2];
          a2[0]=fmaf(wC,hh0,a2[0]); a2[1]=fmaf(wC,hh1,a2[1]); a2[2]=fmaf(wC,hh2v,a2[2]); a2[3]=fmaf(wC,hh3,a2[3]);
        }
      }
      #pragma unroll
      for(int ee=0;ee<4;ee++){
        int eo=e0+ee;
        if(eo<EE){
          g_r[(size_t)eo*640+t+64*m0]=a0[ee];
          g_r[(size_t)eo*640+t+64*m1]=a1[ee];
          if(nm==3) g_r[(size_t)eo*640+t+64*m2]=a2[ee];
        }
      }
    }
    __syncthreads();
  }
}

// ---------------- per-edge kernel: mma xe/msg/rotate ----------------
__global__ __launch_bounds__(512,1)
void k_edge(const float* __restrict__ wigner, const int* __restrict__ ei,
            const float* __restrict__ W1, const float* __restrict__ W0,
            const float* __restrict__ adot, const float* __restrict__ tg,
            const float* __restrict__ fg)
{
  extern __shared__ float sm[];
  unsigned* sW1p = (unsigned*)sm; // 128*72
  float* sW0 = sm+9216;     // 24576
  float* sTG = sW0+24576;   // 900
  float* sFG = sTG+900;     // 900
  float* sAD = sFG+900;     // 128
  float* pe  = sAD+128;     // 2*EPG
  int tid=threadIdx.x;
  for(int i=tid;i<8192;i+=512){ int c=i>>6,h=i&63; sW1p[c*72+h]=cvt_tf32(W1[i]); }
  for(int i=tid;i<24576;i+=512){ int o=i>>7,c=i&127; sW0[i]=W0[c*192+o]; }
  for(int i=tid;i<900;i+=512){ sTG[i]=tg[i]; sFG[i]=fg[i]; }
  if(tid<128) sAD[tid]=adot[tid];
  __syncthreads();

  int grp = tid>>8, t = tid&255;
  float* base  = pe + grp*EPG;
  float* swigA = base;          // 900 (25x36)
  float* swigB = base+900;      // 900
  float* scat  = base+1800;     // 3300 (25x132)
  float* srr   = base+5100;     // 640
  float* sxe   = base+5740;     // 3300 (25x132)
  float* sextra= base+9040;     // 192
  float* smsg  = base+9232;     // 1800 (25x72)
  float* sgrid = sxe;
  float* smact = smsg;

  int h4=t&15, rg16=t>>4;
  int w=t>>5, lane=t&31;
  int mt=w&1, ng=w>>1;
  int fr=lane>>2, cq=lane&3;
  int rowA=mt*16+fr, rowB=rowA+8;

  int stride = (int)gridDim.x*2;
  int e = (int)blockIdx.x*2 + grp;
  int p = 0;

  {
    const float* wp=wigner+(size_t)e*625;
    for(int i=t;i<625;i+=256) swigA[(i/25)*36+(i%25)]=wp[i];
    int src=ei[e], dst=ei[EE+e];
    const float4* hs=(const float4*)(g_h+(size_t)src*1600);
    const float4* hd=(const float4*)(g_h+(size_t)dst*1600);
    float4* cat4=(float4*)scat;
    for(int i=t;i<800;i+=256){ int j=i>>5,qq=i&31; cat4[j*33+qq]=(qq<16)?hs[j*16+qq]:hd[j*16+qq-16]; }
    const float4* rp4=(const float4*)(g_r+(size_t)e*640);
    float4* srr4=(float4*)srr;
    for(int i=t;i<160;i+=256) srr4[i]=rp4[i];
  }

  for(; e<EE; e+=stride){
    int en = e + stride; if(en >= EE) en = e;
    float* swig  = p? swigB : swigA;
    float* swigN = p? swigA : swigB;
    GBAR();

    // xe = (wig @ cat)*r[EXPAND] : mma K=24 + fp32 tail k=24
    {
      float acc[4][4]={};
      #pragma unroll
      for(int kc=0;kc<3;kc++){
        int k0=kc*8;
        unsigned a0=cvt_tf32(swig[rowA*36+k0+cq]);
        unsigned a1=cvt_tf32(swig[rowB*36+k0+cq]);
        unsigned a2=cvt_tf32(swig[rowA*36+k0+cq+4]);
        unsigned a3=cvt_tf32(swig[rowB*36+k0+cq+4]);
        #pragma unroll
        for(int nt=0;nt<4;nt++){
          int nb=ng*32+nt*8;
          unsigned b0=cvt_tf32(scat[(k0+cq)*132+nb+fr]);
          unsigned b1=cvt_tf32(scat[(k0+cq+4)*132+nb+fr]);
          mma_tf32(acc[nt][0],acc[nt][1],acc[nt][2],acc[nt][3],a0,a1,a2,a3,b0,b1);
        }
      }
      float wa0=swig[rowA*36+24], wa1=swig[rowB*36+24];
      int lof0=c_lof[rowA<25?rowA:0], lof1=c_lof[rowB<25?rowB:0];
      #pragma unroll
      for(int nt=0;nt<4;nt++){
        int col=ng*32+nt*8+2*cq;
        float bt0=scat[24*132+col], bt1=scat[24*132+col+1];
        acc[nt][0]=fmaf(wa0,bt0,acc[nt][0]); acc[nt][1]=fmaf(wa0,bt1,acc[nt][1]);
        acc[nt][2]=fmaf(wa1,bt0,acc[nt][2]); acc[nt][3]=fmaf(wa1,bt1,acc[nt][3]);
        if(rowA<25){
          sxe[rowA*132+col]  =acc[nt][0]*srr[lof0*128+col];
          sxe[rowA*132+col+1]=acc[nt][1]*srr[lof0*128+col+1];
        }
        if(rowB<25){
          sxe[rowB*132+col]  =acc[nt][2]*srr[lof1*128+col];
          sxe[rowB*132+col+1]=acc[nt][3]*srr[lof1*128+col+1];
        }
      }
    }
    GBAR();

    // prefetch next edge
    {
      const float* wp=wigner+(size_t)en*625;
      for(int i=t;i<625;i+=256) swigN[(i/25)*36+(i%25)]=wp[i];
      int nsrc=ei[en], ndst=ei[EE+en];
      const float4* hs=(const float4*)(g_h+(size_t)nsrc*1600);
      const float4* hd=(const float4*)(g_h+(size_t)ndst*1600);
      float4* cat4=(float4*)scat;
      for(int i=t;i<800;i+=256){ int j=i>>5,qq=i&31; cat4[j*33+qq]=(qq<16)?hs[j*16+qq]:hd[j*16+qq-16]; }
      const float4* rp4=(const float4*)(g_r+(size_t)en*640);
      float4* srr4=(float4*)srr;
      for(int i=t;i<160;i+=256) srr4[i]=rp4[i];
    }

    // msg = xe @ W1 (mma K=128), extra by t<192
    {
      const float* A0=sxe+rowA*132;
      const float* A1=sxe+rowB*132;
      float acc[2][4]={};
      #pragma unroll
      for(int kc=0;kc<16;kc++){
        int k0=kc*8;
        unsigned a0=cvt_tf32(A0[k0+cq]);
        unsigned a1=cvt_tf32(A1[k0+cq]);
        unsigned a2=cvt_tf32(A0[k0+cq+4]);
        unsigned a3=cvt_tf32(A1[k0+cq+4]);
        #pragma unroll
        for(int nt=0;nt<2;nt++){
          int nb=ng*16+nt*8;
          unsigned b0=sW1p[(k0+cq)*72+nb+fr];
          unsigned b1=sW1p[(k0+cq+4)*72+nb+fr];
          mma_tf32(acc[nt][0],acc[nt][1],acc[nt][2],acc[nt][3],a0,a1,a2,a3,b0,b1);
        }
      }
      #pragma unroll
      for(int nt=0;nt<2;nt++){
        int col=ng*16+nt*8+2*cq;
        if(rowA<25){ smsg[rowA*72+col]=acc[nt][0]; smsg[rowA*72+col+1]=acc[nt][1]; }
        if(rowB<25){ smsg[rowB*72+col]=acc[nt][2]; smsg[rowB*72+col+1]=acc[nt][3]; }
      }
    }
    if(t<192){
      const float4* x0=(const float4*)sxe;
      const float4* wv4=(const float4*)(sW0+t*128);
      float4 acc=Z4;
      #pragma unroll 8
      for(int k=0;k<32;k++){ float4 xv=x0[k], wv=wv4[k];
        acc.x=fmaf(xv.x,wv.x,acc.x); acc.y=fmaf(xv.y,wv.y,acc.y);
        acc.z=fmaf(xv.z,wv.z,acc.z); acc.w=fmaf(xv.w,wv.w,acc.w); }
      sextra[t]=acc.x+acc.y+acc.z+acc.w;
    }
    GBAR();

    // grid = silu(to_grid @ msg) (FFMA2) + alpha
    if(t<8){
      float acc=0.f;
      #pragma unroll
      for(int a=0;a<16;a++){ float v=sextra[t*16+a]; acc=fmaf(silu(v),sAD[t*16+a],acc); }
      g_alpha[e*8+t]=acc;
    }
    {
      int g0=rg16, g1=rg16+16, g2v=rg16+32; bool v2=(g2v<36);
      const ulonglong2* m4=(const ulonglong2*)smsg;
      float4* gr4=(float4*)sgrid;
      ulonglong2 a0=ZP2,a1=ZP2,a2=ZP2;
      #pragma unroll
      for(int i=0;i<25;i++){
        ulonglong2 mv=m4[i*18+h4];
        u64 s0=bc2(sTG[g0*25+i]), s1=bc2(sTG[g1*25+i]);
        FMAP(a0,mv,s0); FMAP(a1,mv,s1);
        if(v2){ u64 s2=bc2(sTG[g2v*25+i]); FMAP(a2,mv,s2); }
      }
      gr4[g0*16+h4]=silu4(tof4(a0));
      gr4[g1*16+h4]=silu4(tof4(a1));
      if(v2) gr4[g2v*16+h4]=silu4(tof4(a2));
    }
    GBAR();

    // mact = [silu(gate); from_grid @ grid] (FFMA2)
    {
      int r0=rg16, r1=rg16+16; bool v1=(r1<25);
      const ulonglong2* gr4=(const ulonglong2*)sgrid;
      ulonglong2 a0=ZP2,a1=ZP2;
      #pragma unroll 6
      for(int g=0;g<36;g++){
        ulonglong2 gv=gr4[g*16+h4];
        if(rg16>0){ u64 s0=bc2(sFG[r0*36+g]); FMAP(a0,gv,s0); }
        if(v1){ u64 s1=bc2(sFG[r1*36+g]); FMAP(a1,gv,s1); }
      }
      if(rg16==0) a0=tou2(silu4(((const float4*)(sextra+128))[h4]));
      ((ulonglong2*)smact)[r0*18+h4]=a0;
      if(v1) ((ulonglong2*)smact)[r1*18+h4]=a1;
    }
    GBAR();

    // rotated = wig^T @ mact (mma K=24 + fp32 tail k=24)
    {
      float acc[2][4]={};
      #pragma unroll
      for(int kc=0;kc<3;kc++){
        int k0=kc*8;
        unsigned a0=cvt_tf32(swig[(k0+cq)*36+rowA]);
        unsigned a1=cvt_tf32(swig[(k0+cq)*36+rowB]);
        unsigned a2=cvt_tf32(swig[(k0+cq+4)*36+rowA]);
        unsigned a3=cvt_tf32(swig[(k0+cq+4)*36+rowB]);
        #pragma unroll
        for(int nt=0;nt<2;nt++){
          int nb=ng*16+nt*8;
          unsigned b0=cvt_tf32(smact[(k0+cq)*72+nb+fr]);
          unsigned b1=cvt_tf32(smact[(k0+cq+4)*72+nb+fr]);
          mma_tf32(acc[nt][0],acc[nt][1],acc[nt][2],acc[nt][3],a0,a1,a2,a3,b0,b1);
        }
      }
      float wa0=swig[24*36+rowA], wa1=swig[24*36+rowB];
      float* op=g_msg+(size_t)e*1600;
      #pragma unroll
      for(int nt=0;nt<2;nt++){
        int col=ng*16+nt*8+2*cq;
        float bt0=smact[24*72+col], bt1=smact[24*72+col+1];
        acc[nt][0]=fmaf(wa0,bt0,acc[nt][0]); acc[nt][1]=fmaf(wa0,bt1,acc[nt][1]);
        acc[nt][2]=fmaf(wa1,bt0,acc[nt][2]); acc[nt][3]=fmaf(wa1,bt1,acc[nt][3]);
        if(rowA<25) *(float2*)(op+rowA*64+col)=make_float2(acc[nt][0],acc[nt][1]);
        if(rowB<25) *(float2*)(op+rowB*64+col)=make_float2(acc[nt][2],acc[nt][3]);
      }
    }
    p ^= 1;
  }
}

// ---------------- node: fused softmax+gather+proj+rmsnorm2+FFN (mma F1/out) ----------------
__global__ __launch_bounds__(512,1)
void k_node(const float* __restrict__ x, float* __restrict__ out,
            const float* __restrict__ po, const float* __restrict__ g2w,
            const float* __restrict__ glw, const float* __restrict__ glb,
            const float* __restrict__ fw1, const float* __restrict__ fb1,
            const float* __restrict__ fw2, const float* __restrict__ fb2,
            const float* __restrict__ tg, const float* __restrict__ fg)
{
  extern __shared__ float sm[];
  float* sPO  = sm;                     // 4096
  float* sGL  = sPO+4096;               // 8192
  unsigned* sW1fp=(unsigned*)(sGL+8192);// 64*136=8704
  unsigned* sW2p =(unsigned*)(sGL+16896);// 128*72=9216
  float* sTG  = sGL+26112-8192+8192;    // = sm+30208
  sTG = sm+30208;                       // 900
  float* sFG  = sTG+900;                // 900
  float* sGLB = sFG+900;                // 128
  float* sB1  = sGLB+128;               // 128
  float* sB2  = sB1+128;                // 64
  float* sGam = sB2+64;                 // 64
  float* pn   = sGam+64;                // 2*NPG
  int tid=threadIdx.x;
  for(int i=tid;i<4096;i+=512) sPO[i]=po[i];
  for(int i=tid;i<8192;i+=512) sGL[i]=glw[i];
  for(int i=tid;i<8192;i+=512){ int c=i>>7,f=i&127; sW1fp[c*136+f]=cvt_tf32(fw1[i]); }
  for(int i=tid;i<8192;i+=512){ int f=i>>6,c=i&63; sW2p[f*72+c]=cvt_tf32(fw2[i]); }
  for(int i=tid;i<900;i+=512){ sTG[i]=tg[i]; sFG[i]=fg[i]; }
  if(tid<128){ sGLB[tid]=glb[tid]; sB1[tid]=fb1[tid]; }
  if(tid<64){ sB2[tid]=fb2[tid]; sGam[tid]=g2w[tid]; }
  __syncthreads();

  int grp=tid>>8, t=tid&255;
  float* base = pn + grp*NPG;
  float* sCE  = base;          // 64
  float* sAL  = base+64;       // 512
  float* sEW  = base+576;      // 512
  float* sXN  = base+1088;     // 1600
  float* sH   = base+2688;     // 1700 (25x68)
  float* sGate= base+4388;     // 128
  float* sF1  = base+4516;     // 3300 (25x132)
  float* sG2  = base+7816;     // 4608
  float* sA   = sG2;
  int* sCEi = (int*)sCE;

  int c4=t&15, rg=t>>4;
  int f4=t&31, rg8=t>>5;
  int w=t>>5, lane=t&31;
  int mt=w&1, ng=w>>1;
  int fr=lane>>2, cq=lane&3;
  int rowA=mt*16+fr, rowB=rowA+8;

  for(int nb=blockIdx.x*2; nb<NN; nb+=gridDim.x*2){
    int n = nb + grp;
    int beg=g_rp[n], end=g_rp[n+1];
    int deg=end-beg;
    float4* sA4=(float4*)sA;
    for(int i=t;i<400;i+=256) sA4[i]=Z4;
    if(t<16) sGate[t] = (t<8)? -3.0e38f : 0.f;
    GBAR();

    for(int k0=beg; k0<end; k0+=64){
      int kc=min(64,end-k0);
      for(int idx=t; idx<kc; idx+=256) sCEi[idx]=g_ce[k0+idx];
      GBAR();
      for(int idx=t; idx<kc*2; idx+=256){
        int j=idx>>1, q=idx&1;
        ((float4*)sAL)[j*2+q] = ((const float4*)(g_alpha+(size_t)sCEi[j]*8))[q];
      }
      GBAR();
      if(t<8){
        float m=sGate[t], s=sGate[8+t];
        for(int j=0;j<kc;j++){
          float a=sAL[j*8+t];
          if(a>m){ s=s*__expf(m-a)+1.f; m=a; }
          else    s+=__expf(a-m);
        }
        sGate[t]=m; sGate[8+t]=s;
      }
      GBAR();
    }
    if(t<8) sGate[8+t]=1.f/(sGate[8+t]+1e-8f);
    GBAR();

    for(int k0=beg; k0<end; k0+=64){
      int kc=min(64,end-k0);
      if(deg>64){
        for(int idx=t; idx<kc; idx+=256) sCEi[idx]=g_ce[k0+idx];
        GBAR();
        for(int idx=t; idx<kc*2; idx+=256){
          int j=idx>>1, q=idx&1;
          ((float4*)sAL)[j*2+q] = ((const float4*)(g_alpha+(size_t)sCEi[j]*8))[q];
        }
      }
      GBAR();
      for(int idx=t; idx<kc*8; idx+=256)
        sEW[idx]=__expf(sAL[idx]-sGate[idx&7])*sGate[8+(idx&7)];
      GBAR();
      for(int j=0;j<kc;j++){
        int e=sCEi[j];
        const float4* mp=(const float4*)(g_msg+(size_t)e*1600);
        const float* wj = sEW + j*8;
        for(int i=t;i<400;i+=256){
          float wv=wj[(i&15)>>1];
          float4 v=mp[i];
          float4 a=sA4[i];
          FMA4(a,wv,v);
          sA4[i]=a;
        }
      }
      GBAR();
    }

    // XN = x + agg @ proj_out (FFMA2)
    {
      int r0=rg, r1=rg+16; bool v1=(r1<25);
      const float4* x4g=(const float4*)(x+(size_t)n*1600);
      const ulonglong2* p4=(const ulonglong2*)sPO;
      ulonglong2 a0=tou2(x4g[r0*16+c4]);
      ulonglong2 a1=tou2(v1? x4g[r1*16+c4] : Z4);
      #pragma unroll 8
      for(int k=0;k<64;k++){
        ulonglong2 wv=p4[k*16+c4];
        u64 s0=bc2(sA[r0*64+k]); FMAP(a0,wv,s0);
        if(v1){ u64 s1=bc2(sA[r1*64+k]); FMAP(a1,wv,s1); }
      }
      ((ulonglong2*)sXN)[r0*16+c4]=a0;
      if(v1) ((ulonglong2*)sXN)[r1*16+c4]=a1;
    }
    GBAR();
    if(t<64){
      float s=0.f;
      #pragma unroll
      for(int i=0;i<NC;i++){ float v=sXN[i*64+t]; s=fmaf(v,v,s); }
      sGate[t]=rsqrtf(s*(1.f/25.f)+1e-6f)*sGam[t];
    }
    GBAR();
    {
      float4* sH4=(float4*)sH;
      const float4* xn4=(const float4*)sXN;
      const float4* rv4=(const float4*)sGate;
      for(int i=t;i<400;i+=256){
        int row=i>>4, q=i&15;
        float4 v=xn4[i], r=rv4[q]; MUL4(v,r);
        sH4[row*17+q]=v;
      }
    }
    GBAR();
    float gacc=0.f;
    if(t<128){
      gacc=sGLB[t];
      #pragma unroll 8
      for(int c=0;c<64;c++) gacc=fmaf(sH[c],sGL[c*128+t],gacc);
    }
    GBAR();
    if(t<128) sGate[t]=gacc;
    // F1 = h @ ffn_w1 (+b1 row0) via mma K=64
    {
      float acc[4][4]={};
      #pragma unroll
      for(int kc=0;kc<8;kc++){
        int k0=kc*8;
        unsigned a0=cvt_tf32(sH[rowA*68+k0+cq]);
        unsigned a1=cvt_tf32(sH[rowB*68+k0+cq]);
        unsigned a2=cvt_tf32(sH[rowA*68+k0+cq+4]);
        unsigned a3=cvt_tf32(sH[rowB*68+k0+cq+4]);
        #pragma unroll
        for(int nt=0;nt<4;nt++){
          int nbb=ng*32+nt*8;
          unsigned b0=sW1fp[(k0+cq)*136+nbb+fr];
          unsigned b1=sW1fp[(k0+cq+4)*136+nbb+fr];
          mma_tf32(acc[nt][0],acc[nt][1],acc[nt][2],acc[nt][3],a0,a1,a2,a3,b0,b1);
        }
      }
      #pragma unroll
      for(int nt=0;nt<4;nt++){
        int col=ng*32+nt*8+2*cq;
        if(rowA<25){
          float v0=acc[nt][0], v1=acc[nt][1];
          if(rowA==0){ v0+=sB1[col]; v1+=sB1[col+1]; }
          sF1[rowA*132+col]=v0; sF1[rowA*132+col+1]=v1;
        }
        if(rowB<25){ sF1[rowB*132+col]=acc[nt][2]; sF1[rowB*132+col+1]=acc[nt][3]; }
      }
    }
    GBAR();
    // G2 = silu(to_grid @ F1) (FFMA2)
    {
      int g0=rg8, g1=rg8+8, g2v=rg8+16, g3=rg8+24, g4v=rg8+32; bool v4=(g4v<36);
      const ulonglong2* F4p=(const ulonglong2*)sF1;
      float4* G4=(float4*)sG2;
      ulonglong2 a0=ZP2,a1=ZP2,a2=ZP2,a3=ZP2,a4=ZP2;
      #pragma unroll
      for(int i=0;i<25;i++){
        ulonglong2 fv=F4p[i*33+f4];
        u64 s0=bc2(sTG[g0*25+i]), s1=bc2(sTG[g1*25+i]);
        u64 s2=bc2(sTG[g2v*25+i]), s3=bc2(sTG[g3*25+i]);
        FMAP(a0,fv,s0); FMAP(a1,fv,s1); FMAP(a2,fv,s2); FMAP(a3,fv,s3);
        if(v4){ u64 s4=bc2(sTG[g4v*25+i]); FMAP(a4,fv,s4); }
      }
      G4[g0*32+f4]=silu4(tof4(a0)); G4[g1*32+f4]=silu4(tof4(a1));
      G4[g2v*32+f4]=silu4(tof4(a2)); G4[g3*32+f4]=silu4(tof4(a3));
      if(v4) G4[g4v*32+f4]=silu4(tof4(a4));
    }
    GBAR();
    // F1 := [silu(gate); from_grid @ G2] (FFMA2)
    {
      int r0=rg8, r1=rg8+8, r2=rg8+16;
      const ulonglong2* G4=(const ulonglong2*)sG2;
      ulonglong2 a0=ZP2,a1=ZP2,a2=ZP2,a3=ZP2;
      #pragma unroll 6
      for(int g=0;g<36;g++){
        ulonglong2 gv=G4[g*32+f4];
        if(rg8>0){ u64 s0=bc2(sFG[r0*36+g]); FMAP(a0,gv,s0); }
        u64 s1=bc2(sFG[r1*36+g]), s2=bc2(sFG[r2*36+g]);
        FMAP(a1,gv,s1); FMAP(a2,gv,s2);
        if(rg8==0){ u64 s3=bc2(sFG[24*36+g]); FMAP(a3,gv,s3); }
      }
      if(rg8==0) a0=tou2(silu4(((const float4*)sGate)[f4]));
      ulonglong2* F2v=(ulonglong2*)sF1;
      F2v[r0*33+f4]=a0; F2v[r1*33+f4]=a1; F2v[r2*33+f4]=a2;
      if(rg8==0) F2v[24*33+f4]=a3;
    }
    GBAR();
    // out = XN + F1 @ ffn_w2 (+b2 row0) via mma K=128
    {
      float acc[2][4]={};
      #pragma unroll
      for(int kc=0;kc<16;kc++){
        int k0=kc*8;
        unsigned a0=cvt_tf32(sF1[rowA*132+k0+cq]);
        unsigned a1=cvt_tf32(sF1[rowB*132+k0+cq]);
        unsigned a2=cvt_tf32(sF1[rowA*132+k0+cq+4]);
        unsigned a3=cvt_tf32(sF1[rowB*132+k0+cq+4]);
        #pragma unroll
        for(int nt=0;nt<2;nt++){
          int nbb=ng*16+nt*8;
          unsigned b0=sW2p[(k0+cq)*72+nbb+fr];
          unsigned b1=sW2p[(k0+cq+4)*72+nbb+fr];
          mma_tf32(acc[nt][0],acc[nt][1],acc[nt][2],acc[nt][3],a0,a1,a2,a3,b0,b1);
        }
      }
      float* op=out+(size_t)n*1600;
      #pragma unroll
      for(int nt=0;nt<2;nt++){
        int col=ng*16+nt*8+2*cq;
        if(rowA<25){
          float v0=sXN[rowA*64+col]+acc[nt][0];
          float v1=sXN[rowA*64+col+1]+acc[nt][1];
          if(rowA==0){ v0+=sB2[col]; v1+=sB2[col+1]; }
          *(float2*)(op+rowA*64+col)=make_float2(v0,v1);
        }
        if(rowB<25){
          float v0=sXN[rowB*64+col]+acc[nt][2];
          float v1=sXN[rowB*64+col+1]+acc[nt][3];
          *(float2*)(op+rowB*64+col)=make_float2(v0,v1);
        }
      }
    }
    GBAR();
  }
}

extern "C" void kernel_launch(void* const* d_in, const int* in_sizes, int n_in,
                              void* d_out, int out_size) {
  const float* x    = (const float*)d_in[0];
  const int*   ei   = (const int*)d_in[1];
  const int*   zn   = (const int*)d_in[2];
  const float* ed   = (const float*)d_in[3];
  const float* wigr = (const float*)d_in[4];
  const float* stab = (const float*)d_in[5];
  const float* ttab = (const float*)d_in[6];
  const float* rw1  = (const float*)d_in[7];
  const float* rb1  = (const float*)d_in[8];
  const float* rw2  = (const float*)d_in[9];
  const float* rb2  = (const float*)d_in[10];
  const float* rw3  = (const float*)d_in[11];
  const float* rb3  = (const float*)d_in[12];
  const float* W1   = (const float*)d_in[13];
  const float* W0e  = (const float*)d_in[14];
  const float* adot = (const float*)d_in[15];
  const float* tg   = (const float*)d_in[16];
  const float* fg   = (const float*)d_in[17];
  const float* po   = (const float*)d_in[18];
  const float* gm1  = (const float*)d_in[19];
  const float* gm2  = (const float*)d_in[20];
  const float* glw  = (const float*)d_in[21];
  const float* glb  = (const float*)d_in[22];
  const float* fw1  = (const float*)d_in[23];
  const float* fb1  = (const float*)d_in[24];
  const float* fw2  = (const float*)d_in[25];
  const float* fb2  = (const float*)d_in[26];
  float* out = (float*)d_out;

  void *pcnt;
  cudaGetSymbolAddress(&pcnt, g_cnt);
  cudaMemsetAsync(pcnt, 0, NN*sizeof(int));

  const int RAD_SMEM  = 52864*4;
  const int EDGE_SMEM = (9216+24576+900+900+128 + 2*EPG)*4;   // 231136
  const int NODE_SMEM = (32392 + 2*NPG)*4;                    // 228960
  cudaFuncSetAttribute(k_rad,  cudaFuncAttributeMaxDynamicSharedMemorySize, RAD_SMEM);
  cudaFuncSetAttribute(k_edge, cudaFuncAttributeMaxDynamicSharedMemorySize, EDGE_SMEM);
  cudaFuncSetAttribute(k_node, cudaFuncAttributeMaxDynamicSharedMemorySize, NODE_SMEM);

  k_rms1<<<(NN+3)/4, dim3(64,4)>>>(x, gm1);
  k_count<<<(EE+255)/256, 256>>>(ei);
  k_scan<<<1, 1024>>>();
  k_fill<<<(EE+255)/256, 256>>>(ei);
  k_rad<<<296, 256, RAD_SMEM>>>(ed, ei, zn, stab, ttab, rw1, rb1, rw2, rb2, rw3, rb3);
  k_edge<<<148, 512, EDGE_SMEM>>>(wigr, ei, W1, W0e, adot, tg, fg);
  k_node<<<148, 512, NODE_SMEM>>>(x, out, po, gm2, glw, glb, fw1, fb1, fw2, fb2, tg, fg);
}

// round 15
// speedup vs baseline: 1.3464x; 1.1628x over previous
#include <cuda_runtime.h>

#define NN 10000
#define EE 50000
#define NC 25
#define EPG 11032
#define NPG 12424

typedef unsigned long long u64;

__constant__ int c_lof[NC] = {0,1,1,1,2,2,2,2,2,3,3,3,3,3,3,3,4,4,4,4,4,4,4,4,4};

__device__ float    g_h[(size_t)NN*1600];
__device__ float    g_r[(size_t)EE*640];
__device__ float    g_msg[(size_t)EE*1600];
__device__ float    g_alpha[EE*8];
__device__ int      g_cnt[NN];
__device__ int      g_rp[NN+1];
__device__ int      g_cur[NN];
__device__ int      g_ce[EE];

__device__ __forceinline__ float silu(float x){ return x/(1.f+__expf(-x)); }
__device__ __forceinline__ float4 silu4(float4 v){
  return make_float4(silu(v.x),silu(v.y),silu(v.z),silu(v.w));
}
__device__ __forceinline__ u64 bc2(float s){
  unsigned i=__float_as_uint(s); u64 r;
  asm("mov.b64 %0,{%1,%1};" : "=l"(r) : "r"(i)); return r;
}
__device__ __forceinline__ void f2(u64&a, u64 v, u64 s){
  asm("fma.rn.f32x2 %0,%1,%2,%0;" : "+l"(a) : "l"(v), "l"(s));
}
__device__ __forceinline__ void m2(u64&a, u64 v){
  asm("mul.rn.f32x2 %0,%0,%1;" : "+l"(a) : "l"(v));
}
__device__ __forceinline__ void padd(u64&a, u64 b){
  asm("add.rn.f32x2 %0,%0,%1;" : "+l"(a) : "l"(b));
}
union F4U { float4 f; ulonglong2 u; };
__device__ __forceinline__ float4 tof4(ulonglong2 a){ F4U u; u.u=a; return u.f; }
__device__ __forceinline__ ulonglong2 tou2(float4 f){ F4U u; u.f=f; return u.u; }
__device__ __forceinline__ unsigned cvt_tf32(float f){
  unsigned u; asm("cvt.rna.tf32.f32 %0,%1;" : "=r"(u) : "f"(f)); return u;
}
__device__ __forceinline__ void mma_tf32(float&c0,float&c1,float&c2,float&c3,
                                         unsigned a0,unsigned a1,unsigned a2,unsigned a3,
                                         unsigned b0,unsigned b1){
  asm("mma.sync.aligned.m16n8k8.row.col.f32.tf32.tf32.f32 "
      "{%0,%1,%2,%3},{%4,%5,%6,%7},{%8,%9},{%0,%1,%2,%3};"
      : "+f"(c0),"+f"(c1),"+f"(c2),"+f"(c3)
      : "r"(a0),"r"(a1),"r"(a2),"r"(a3),"r"(b0),"r"(b1));
}
#define FMAP(a,v,s) { f2((a).x,(v).x,(s)); f2((a).y,(v).y,(s)); }
#define FMA4(a,s,v) { (a).x=fmaf((s),(v).x,(a).x); (a).y=fmaf((s),(v).y,(a).y); \
                      (a).z=fmaf((s),(v).z,(a).z); (a).w=fmaf((s),(v).w,(a).w); }
#define MUL4(a,v)   { (a).x*=(v).x; (a).y*=(v).y; (a).z*=(v).z; (a).w*=(v).w; }
#define Z4 make_float4(0.f,0.f,0.f,0.f)
#define ZP2 {0ull,0ull}
#define GBAR() asm volatile("bar.sync %0, %1;" :: "r"(grp+1), "r"(256) : "memory")

// ---------------- rmsnorm1 ----------------
__global__ void k_rms1(const float* __restrict__ x, const float* __restrict__ gamma){
  int n = blockIdx.x*4 + threadIdx.y;
  if(n >= NN) return;
  int c = threadIdx.x;
  const float* xp = x + (size_t)n*1600 + c;
  float s = 0.f;
  #pragma unroll
  for(int i=0;i<NC;i++){ float v = xp[i*64]; s += v*v; }
  float gm = rsqrtf(s*(1.f/25.f) + 1e-6f) * gamma[c];
  float* hp = g_h + (size_t)n*1600 + c;
  #pragma unroll
  for(int i=0;i<NC;i++) hp[i*64] = xp[i*64]*gm;
}

// ---------------- CSR build ----------------
__global__ void k_count(const int* __restrict__ ei){
  int e = blockIdx.x*256 + threadIdx.x;
  if(e < EE) atomicAdd(&g_cnt[ei[EE+e]], 1);
}
__global__ void k_scan(){
  __shared__ int ps[1024];
  int t = threadIdx.x;
  int v[10]; int s = 0;
  #pragma unroll
  for(int m=0;m<10;m++){ int i=t*10+m; int c=(i<NN)? g_cnt[i]:0; v[m]=s; s+=c; }
  ps[t]=s; __syncthreads();
  for(int off=1; off<1024; off<<=1){
    int val=(t>=off)? ps[t-off]:0; __syncthreads();
    ps[t]+=val; __syncthreads();
  }
  int excl=(t>0)? ps[t-1]:0;
  #pragma unroll
  for(int m=0;m<10;m++){
    int i=t*10+m;
    if(i<NN){ int o=excl+v[m]; g_rp[i]=o; g_cur[i]=o; }
  }
  if(t==0) g_rp[NN]=EE;
}
__global__ void k_fill(const int* __restrict__ ei){
  int e = blockIdx.x*256 + threadIdx.x;
  if(e < EE) g_ce[atomicAdd(&g_cur[ei[EE+e]],1)] = e;
}

// ---------------- radial MLP ----------------
__global__ __launch_bounds__(256,1)
void k_rad(const float* __restrict__ ed, const int* __restrict__ ei,
           const int* __restrict__ zn,
           const float* __restrict__ st, const float* __restrict__ tt,
           const float* __restrict__ w1, const float* __restrict__ b1,
           const float* __restrict__ w2, const float* __restrict__ b2,
           const float* __restrict__ w3, const float* __restrict__ b3)
{
  extern __shared__ float sm[];
  float* sw1=sm; float* sw2=sw1+6144; float* sw3=sw2+4096;
  float* sb1=sw3+40960; float* sb2=sb1+64; float* sb3=sb2+64;
  float* ef=sb3+640; float* h1=ef+384; float* h2=h1+256;
  int tid=threadIdx.x;
  for(int i=tid;i<6144;i+=256)  sw1[i]=w1[i];
  for(int i=tid;i<4096;i+=256)  sw2[i]=w2[i];
  for(int i=tid;i<40960;i+=256) sw3[i]=w3[i];
  if(tid<64){ sb1[tid]=b1[tid]; sb2[tid]=b2[tid]; }
  for(int i=tid;i<640;i+=256)   sb3[i]=b3[i];
  __syncthreads();

  int grp=tid>>6, t=tid&63;
  int q=grp;
  int nm=(q<2)?3:2;
  int m0=q, m1=q+4, m2=q+8;

  int iters=(EE+(int)gridDim.x*4-1)/((int)gridDim.x*4);
  for(int it=0; it<iters; it++){
    int e0=(it*(int)gridDim.x+(int)blockIdx.x)*4;
    int e=e0+grp;
    bool valid=(e<EE);
    if(t<32){
      if(valid){
        int src=ei[e], dst=ei[EE+e];
        ef[grp*96+t]   =ed[(size_t)e*32+t];
        ef[grp*96+32+t]=st[zn[src]*32+t];
        ef[grp*96+64+t]=tt[zn[dst]*32+t];
      } else {
        ef[grp*96+t]=0.f; ef[grp*96+32+t]=0.f; ef[grp*96+64+t]=0.f;
      }
    }
    __syncthreads();
    {
      float acc=sb1[t];
      const float4* ef4=(const float4*)(ef+grp*96);
      #pragma unroll
      for(int k4=0;k4<24;k4++){
        float4 v=ef4[k4];
        acc=fmaf(v.x,sw1[(k4*4+0)*64+t],acc);
        acc=fmaf(v.y,sw1[(k4*4+1)*64+t],acc);
        acc=fmaf(v.z,sw1[(k4*4+2)*64+t],acc);
        acc=fmaf(v.w,sw1[(k4*4+3)*64+t],acc);
      }
      h1[grp*64+t]=silu(acc);
    }
    __syncthreads();
    {
      float acc=sb2[t];
      const float4* h14=(const float4*)(h1+grp*64);
      #pragma unroll
      for(int k4=0;k4<16;k4++){
        float4 v=h14[k4];
        acc=fmaf(v.x,sw2[(k4*4+0)*64+t],acc);
        acc=fmaf(v.y,sw2[(k4*4+1)*64+t],acc);
        acc=fmaf(v.z,sw2[(k4*4+2)*64+t],acc);
        acc=fmaf(v.w,sw2[(k4*4+3)*64+t],acc);
      }
      h2[grp*64+t]=silu(acc);
    }
    __syncthreads();
    {
      float a0[4], a1[4], a2[4];
      #pragma unroll
      for(int ee=0;ee<4;ee++){ a0[ee]=sb3[t+64*m0]; a1[ee]=sb3[t+64*m1]; a2[ee]=(nm==3)?sb3[t+64*m2]:0.f; }
      for(int k=0;k<64;k++){
        float hh0=h2[k], hh1=h2[64+k], hh2v=h2[128+k], hh3=h2[192+k];
        float wA=sw3[k*640+t+64*m0];
        float wB=sw3[k*640+t+64*m1];
        a0[0]=fmaf(wA,hh0,a0[0]); a0[1]=fmaf(wA,hh1,a0[1]); a0[2]=fmaf(wA,hh2v,a0[2]); a0[3]=fmaf(wA,hh3,a0[3]);
        a1[0]=fmaf(wB,hh0,a1[0]); a1[1]=fmaf(wB,hh1,a1[1]); a1[2]=fmaf(wB,hh2v,a1[2]); a1[3]=fmaf(wB,hh3,a1[3]);
        if(nm==3){
          float wC=sw3[k*640+t+64*m2];
          a2[0]=fmaf(wC,hh0,a2[0]); a2[1]=fmaf(wC,hh1,a2[1]); a2[2]=fmaf(wC,hh2v,a2[2]); a2[3]=fmaf(wC,hh3,a2[3]);
        }
      }
      #pragma unroll
      for(int ee=0;ee<4;ee++){
        int eo=e0+ee;
        if(eo<EE){
          g_r[(size_t)eo*640+t+64*m0]=a0[ee];
          g_r[(size_t)eo*640+t+64*m1]=a1[ee];
          if(nm==3) g_r[(size_t)eo*640+t+64*m2]=a2[ee];
        }
      }
    }
    __syncthreads();
  }
}

// ---------------- per-edge kernel: all-mma pipeline ----------------
__global__ __launch_bounds__(512,1)
void k_edge(const float* __restrict__ wigner, const int* __restrict__ ei,
            const float* __restrict__ W1, const float* __restrict__ W0,
            const float* __restrict__ adot, const float* __restrict__ tg,
            const float* __restrict__ fg)
{
  extern __shared__ float sm[];
  unsigned* sW1p = (unsigned*)sm; // 128*72
  float* sW0 = sm+9216;     // 24576
  float* sTG = sW0+24576;   // 900
  float* sFG = sTG+900;     // 900
  float* sAD = sFG+900;     // 128
  float* pe  = sAD+128;     // 2*EPG
  int tid=threadIdx.x;
  for(int i=tid;i<8192;i+=512){ int c=i>>6,h=i&63; sW1p[c*72+h]=cvt_tf32(W1[i]); }
  for(int i=tid;i<24576;i+=512){ int o=i>>7,c=i&127; sW0[i]=W0[c*192+o]; }
  for(int i=tid;i<900;i+=512){ sTG[i]=tg[i]; sFG[i]=fg[i]; }
  if(tid<128) sAD[tid]=adot[tid];
  __syncthreads();

  int grp = tid>>8, t = tid&255;
  float* base  = pe + grp*EPG;
  float* swigA = base;          // 900 (25x36)
  float* swigB = base+900;      // 900
  float* scat  = base+1800;     // 3300 (25x132)
  float* srr   = base+5100;     // 640
  float* sxe   = base+5740;     // 3300 (25x132); reused as sgrid (40x72=2880)
  float* sextra= base+9040;     // 192
  float* smsg  = base+9232;     // 1800 (25x72)
  float* sgrid = sxe;
  float* smact = smsg;

  int w=t>>5, lane=t&31;
  int mt=w&1, ng=w>>1;
  int fr=lane>>2, cq=lane&3;
  int rowA=mt*16+fr, rowB=rowA+8;

  int stride = (int)gridDim.x*2;
  int e = (int)blockIdx.x*2 + grp;
  int p = 0;

  {
    const float* wp=wigner+(size_t)e*625;
    for(int i=t;i<625;i+=256) swigA[(i/25)*36+(i%25)]=wp[i];
    int src=ei[e], dst=ei[EE+e];
    const float4* hs=(const float4*)(g_h+(size_t)src*1600);
    const float4* hd=(const float4*)(g_h+(size_t)dst*1600);
    float4* cat4=(float4*)scat;
    for(int i=t;i<800;i+=256){ int j=i>>5,qq=i&31; cat4[j*33+qq]=(qq<16)?hs[j*16+qq]:hd[j*16+qq-16]; }
    const float4* rp4=(const float4*)(g_r+(size_t)e*640);
    float4* srr4=(float4*)srr;
    for(int i=t;i<160;i+=256) srr4[i]=rp4[i];
  }

  for(; e<EE; e+=stride){
    int en = e + stride; if(en >= EE) en = e;
    float* swig  = p? swigB : swigA;
    float* swigN = p? swigA : swigB;
    GBAR();

    // xe = (wig @ cat)*r[EXPAND] : mma K=24 + fp32 tail k=24
    {
      float acc[4][4]={};
      #pragma unroll
      for(int kc=0;kc<3;kc++){
        int k0=kc*8;
        unsigned a0=cvt_tf32(swig[rowA*36+k0+cq]);
        unsigned a1=cvt_tf32(swig[rowB*36+k0+cq]);
        unsigned a2=cvt_tf32(swig[rowA*36+k0+cq+4]);
        unsigned a3=cvt_tf32(swig[rowB*36+k0+cq+4]);
        #pragma unroll
        for(int nt=0;nt<4;nt++){
          int nb=ng*32+nt*8;
          unsigned b0=cvt_tf32(scat[(k0+cq)*132+nb+fr]);
          unsigned b1=cvt_tf32(scat[(k0+cq+4)*132+nb+fr]);
          mma_tf32(acc[nt][0],acc[nt][1],acc[nt][2],acc[nt][3],a0,a1,a2,a3,b0,b1);
        }
      }
      float wa0=swig[rowA*36+24], wa1=swig[rowB*36+24];
      int lof0=c_lof[rowA<25?rowA:0], lof1=c_lof[rowB<25?rowB:0];
      #pragma unroll
      for(int nt=0;nt<4;nt++){
        int col=ng*32+nt*8+2*cq;
        float bt0=scat[24*132+col], bt1=scat[24*132+col+1];
        acc[nt][0]=fmaf(wa0,bt0,acc[nt][0]); acc[nt][1]=fmaf(wa0,bt1,acc[nt][1]);
        acc[nt][2]=fmaf(wa1,bt0,acc[nt][2]); acc[nt][3]=fmaf(wa1,bt1,acc[nt][3]);
        if(rowA<25){
          sxe[rowA*132+col]  =acc[nt][0]*srr[lof0*128+col];
          sxe[rowA*132+col+1]=acc[nt][1]*srr[lof0*128+col+1];
        }
        if(rowB<25){
          sxe[rowB*132+col]  =acc[nt][2]*srr[lof1*128+col];
          sxe[rowB*132+col+1]=acc[nt][3]*srr[lof1*128+col+1];
        }
      }
    }
    GBAR();

    // prefetch next edge
    {
      const float* wp=wigner+(size_t)en*625;
      for(int i=t;i<625;i+=256) swigN[(i/25)*36+(i%25)]=wp[i];
      int nsrc=ei[en], ndst=ei[EE+en];
      const float4* hs=(const float4*)(g_h+(size_t)nsrc*1600);
      const float4* hd=(const float4*)(g_h+(size_t)ndst*1600);
      float4* cat4=(float4*)scat;
      for(int i=t;i<800;i+=256){ int j=i>>5,qq=i&31; cat4[j*33+qq]=(qq<16)?hs[j*16+qq]:hd[j*16+qq-16]; }
      const float4* rp4=(const float4*)(g_r+(size_t)en*640);
      float4* srr4=(float4*)srr;
      for(int i=t;i<160;i+=256) srr4[i]=rp4[i];
    }

    // msg = xe @ W1 (mma K=128), extra by t<192
    {
      const float* A0=sxe+rowA*132;
      const float* A1=sxe+rowB*132;
      float acc[2][4]={};
      #pragma unroll
      for(int kc=0;kc<16;kc++){
        int k0=kc*8;
        unsigned a0=cvt_tf32(A0[k0+cq]);
        unsigned a1=cvt_tf32(A1[k0+cq]);
        unsigned a2=cvt_tf32(A0[k0+cq+4]);
        unsigned a3=cvt_tf32(A1[k0+cq+4]);
        #pragma unroll
        for(int nt=0;nt<2;nt++){
          int nb=ng*16+nt*8;
          unsigned b0=sW1p[(k0+cq)*72+nb+fr];
          unsigned b1=sW1p[(k0+cq+4)*72+nb+fr];
          mma_tf32(acc[nt][0],acc[nt][1],acc[nt][2],acc[nt][3],a0,a1,a2,a3,b0,b1);
        }
      }
      #pragma unroll
      for(int nt=0;nt<2;nt++){
        int col=ng*16+nt*8+2*cq;
        if(rowA<25){ smsg[rowA*72+col]=acc[nt][0]; smsg[rowA*72+col+1]=acc[nt][1]; }
        if(rowB<25){ smsg[rowB*72+col]=acc[nt][2]; smsg[rowB*72+col+1]=acc[nt][3]; }
      }
    }
    if(t<192){
      const float4* x0=(const float4*)sxe;
      const float4* wv4=(const float4*)(sW0+t*128);
      float4 acc=Z4;
      #pragma unroll 8
      for(int k=0;k<32;k++){ float4 xv=x0[k], wv=wv4[k];
        acc.x=fmaf(xv.x,wv.x,acc.x); acc.y=fmaf(xv.y,wv.y,acc.y);
        acc.z=fmaf(xv.z,wv.z,acc.z); acc.w=fmaf(xv.w,wv.w,acc.w); }
      sextra[t]=acc.x+acc.y+acc.z+acc.w;
    }
    GBAR();

    // grid = silu(to_grid @ msg) via mma (12 m16n16 tasks), + alpha by t<8
    if(t<8){
      float acc=0.f;
      #pragma unroll
      for(int a=0;a<16;a++){ float v=sextra[t*16+a]; acc=fmaf(silu(v),sAD[t*16+a],acc); }
      g_alpha[e*8+t]=acc;
    }
    {
      #pragma unroll
      for(int tk=0;tk<2;tk++){
        int task = w + tk*8;
        if(task<12){
          int gmt=task>>2, gnq=task&3;
          int rowG=gmt*16+fr, rowG2=rowG+8;
          float acc[2][4]={};
          #pragma unroll
          for(int kc=0;kc<3;kc++){
            int k0=kc*8;
            unsigned a0=cvt_tf32(sTG[rowG*25+k0+cq]);
            unsigned a1=cvt_tf32(sTG[rowG2*25+k0+cq]);
            unsigned a2=cvt_tf32(sTG[rowG*25+k0+cq+4]);
            unsigned a3=cvt_tf32(sTG[rowG2*25+k0+cq+4]);
            #pragma unroll
            for(int nt=0;nt<2;nt++){
              int nb=gnq*16+nt*8;
              unsigned b0=cvt_tf32(smsg[(k0+cq)*72+nb+fr]);
              unsigned b1=cvt_tf32(smsg[(k0+cq+4)*72+nb+fr]);
              mma_tf32(acc[nt][0],acc[nt][1],acc[nt][2],acc[nt][3],a0,a1,a2,a3,b0,b1);
            }
          }
          float wa0=sTG[rowG*25+24], wa1=sTG[rowG2*25+24];
          #pragma unroll
          for(int nt=0;nt<2;nt++){
            int col=gnq*16+nt*8+2*cq;
            float bt0=smsg[24*72+col], bt1=smsg[24*72+col+1];
            acc[nt][0]=fmaf(wa0,bt0,acc[nt][0]); acc[nt][1]=fmaf(wa0,bt1,acc[nt][1]);
            acc[nt][2]=fmaf(wa1,bt0,acc[nt][2]); acc[nt][3]=fmaf(wa1,bt1,acc[nt][3]);
            if(rowG<36){ sgrid[rowG*72+col]=silu(acc[nt][0]); sgrid[rowG*72+col+1]=silu(acc[nt][1]); }
            if(rowG2<36){ sgrid[rowG2*72+col]=silu(acc[nt][2]); sgrid[rowG2*72+col+1]=silu(acc[nt][3]); }
          }
        }
      }
      // zero-pad rows 36..39 (cols 0..63) so mact can run K=40
      { int row=36+(t>>6), col=t&63; sgrid[row*72+col]=0.f; }
    }
    GBAR();

    // mact = [silu(gate); from_grid @ grid] via mma K=40
    {
      float acc[2][4]={};
      #pragma unroll
      for(int kc=0;kc<5;kc++){
        int k0=kc*8;
        unsigned a0=cvt_tf32(sFG[rowA*36+k0+cq]);
        unsigned a1=cvt_tf32(sFG[rowB*36+k0+cq]);
        unsigned a2=cvt_tf32(sFG[rowA*36+k0+cq+4]);
        unsigned a3=cvt_tf32(sFG[rowB*36+k0+cq+4]);
        #pragma unroll
        for(int nt=0;nt<2;nt++){
          int nb=ng*16+nt*8;
          unsigned b0=cvt_tf32(sgrid[(k0+cq)*72+nb+fr]);
          unsigned b1=cvt_tf32(sgrid[(k0+cq+4)*72+nb+fr]);
          mma_tf32(acc[nt][0],acc[nt][1],acc[nt][2],acc[nt][3],a0,a1,a2,a3,b0,b1);
        }
      }
      #pragma unroll
      for(int nt=0;nt<2;nt++){
        int col=ng*16+nt*8+2*cq;
        if(rowA<25){
          float v0=acc[nt][0], v1=acc[nt][1];
          if(rowA==0){ v0=silu(sextra[128+col]); v1=silu(sextra[128+col+1]); }
          smact[rowA*72+col]=v0; smact[rowA*72+col+1]=v1;
        }
        if(rowB<25){ smact[rowB*72+col]=acc[nt][2]; smact[rowB*72+col+1]=acc[nt][3]; }
      }
    }
    GBAR();

    // rotated = wig^T @ mact (mma K=24 + fp32 tail k=24)
    {
      float acc[2][4]={};
      #pragma unroll
      for(int kc=0;kc<3;kc++){
        int k0=kc*8;
        unsigned a0=cvt_tf32(swig[(k0+cq)*36+rowA]);
        unsigned a1=cvt_tf32(swig[(k0+cq)*36+rowB]);
        unsigned a2=cvt_tf32(swig[(k0+cq+4)*36+rowA]);
        unsigned a3=cvt_tf32(swig[(k0+cq+4)*36+rowB]);
        #pragma unroll
        for(int nt=0;nt<2;nt++){
          int nb=ng*16+nt*8;
          unsigned b0=cvt_tf32(smact[(k0+cq)*72+nb+fr]);
          unsigned b1=cvt_tf32(smact[(k0+cq+4)*72+nb+fr]);
          mma_tf32(acc[nt][0],acc[nt][1],acc[nt][2],acc[nt][3],a0,a1,a2,a3,b0,b1);
        }
      }
      float wa0=swig[24*36+rowA], wa1=swig[24*36+rowB];
      float* op=g_msg+(size_t)e*1600;
      #pragma unroll
      for(int nt=0;nt<2;nt++){
        int col=ng*16+nt*8+2*cq;
        float bt0=smact[24*72+col], bt1=smact[24*72+col+1];
        acc[nt][0]=fmaf(wa0,bt0,acc[nt][0]); acc[nt][1]=fmaf(wa0,bt1,acc[nt][1]);
        acc[nt][2]=fmaf(wa1,bt0,acc[nt][2]); acc[nt][3]=fmaf(wa1,bt1,acc[nt][3]);
        if(rowA<25) *(float2*)(op+rowA*64+col)=make_float2(acc[nt][0],acc[nt][1]);
        if(rowB<25) *(float2*)(op+rowB*64+col)=make_float2(acc[nt][2],acc[nt][3]);
      }
    }
    p ^= 1;
  }
}

// ---------------- node: fused softmax+gather+proj+rmsnorm2+FFN (mma F1/out) ----------------
__global__ __launch_bounds__(512,1)
void k_node(const float* __restrict__ x, float* __restrict__ out,
            const float* __restrict__ po, const float* __restrict__ g2w,
            const float* __restrict__ glw, const float* __restrict__ glb,
            const float* __restrict__ fw1, const float* __restrict__ fb1,
            const float* __restrict__ fw2, const float* __restrict__ fb2,
            const float* __restrict__ tg, const float* __restrict__ fg)
{
  extern __shared__ float sm[];
  float* sPO  = sm;                     // 4096
  float* sGL  = sPO+4096;               // 8192
  unsigned* sW1fp=(unsigned*)(sGL+8192);// 8704
  unsigned* sW2p =(unsigned*)(sGL+16896);// 9216
  float* sTG  = sm+30208;               // 900
  float* sFG  = sTG+900;                // 900
  float* sGLB = sFG+900;                // 128
  float* sB1  = sGLB+128;               // 128
  float* sB2  = sB1+128;                // 64
  float* sGam = sB2+64;                 // 64
  float* pn   = sGam+64;                // 2*NPG
  int tid=threadIdx.x;
  for(int i=tid;i<4096;i+=512) sPO[i]=po[i];
  for(int i=tid;i<8192;i+=512) sGL[i]=glw[i];
  for(int i=tid;i<8192;i+=512){ int c=i>>7,f=i&127; sW1fp[c*136+f]=cvt_tf32(fw1[i]); }
  for(int i=tid;i<8192;i+=512){ int f=i>>6,c=i&63; sW2p[f*72+c]=cvt_tf32(fw2[i]); }
  for(int i=tid;i<900;i+=512){ sTG[i]=tg[i]; sFG[i]=fg[i]; }
  if(tid<128){ sGLB[tid]=glb[tid]; sB1[tid]=fb1[tid]; }
  if(tid<64){ sB2[tid]=fb2[tid]; sGam[tid]=g2w[tid]; }
  __syncthreads();

  int grp=tid>>8, t=tid&255;
  float* base = pn + grp*NPG;
  float* sCE  = base;
  float* sAL  = base+64;
  float* sEW  = base+576;
  float* sXN  = base+1088;
  float* sH   = base+2688;     // 25x68
  float* sGate= base+4388;
  float* sF1  = base+4516;     // 25x132
  float* sG2  = base+7816;     // 4608 (sA alias)
  float* sA   = sG2;
  int* sCEi = (int*)sCE;

  int c4=t&15, rg=t>>4;
  int f4=t&31, rg8=t>>5;
  int w=t>>5, lane=t&31;
  int mt=w&1, ng=w>>1;
  int fr=lane>>2, cq=lane&3;
  int rowA=mt*16+fr, rowB=rowA+8;

  for(int nb=blockIdx.x*2; nb<NN; nb+=gridDim.x*2){
    int n = nb + grp;
    int beg=g_rp[n], end=g_rp[n+1];
    int deg=end-beg;
    float4* sA4=(float4*)sA;
    for(int i=t;i<400;i+=256) sA4[i]=Z4;
    if(t<16) sGate[t] = (t<8)? -3.0e38f : 0.f;
    GBAR();

    for(int k0=beg; k0<end; k0+=64){
      int kc=min(64,end-k0);
      for(int idx=t; idx<kc; idx+=256) sCEi[idx]=g_ce[k0+idx];
      GBAR();
      for(int idx=t; idx<kc*2; idx+=256){
        int j=idx>>1, q=idx&1;
        ((float4*)sAL)[j*2+q] = ((const float4*)(g_alpha+(size_t)sCEi[j]*8))[q];
      }
      GBAR();
      if(t<8){
        float m=sGate[t], s=sGate[8+t];
        for(int j=0;j<kc;j++){
          float a=sAL[j*8+t];
          if(a>m){ s=s*__expf(m-a)+1.f; m=a; }
          else    s+=__expf(a-m);
        }
        sGate[t]=m; sGate[8+t]=s;
      }
      GBAR();
    }
    if(t<8) sGate[8+t]=1.f/(sGate[8+t]+1e-8f);
    GBAR();

    for(int k0=beg; k0<end; k0+=64){
      int kc=min(64,end-k0);
      if(deg>64){
        for(int idx=t; idx<kc; idx+=256) sCEi[idx]=g_ce[k0+idx];
        GBAR();
        for(int idx=t; idx<kc*2; idx+=256){
          int j=idx>>1, q=idx&1;
          ((float4*)sAL)[j*2+q] = ((const float4*)(g_alpha+(size_t)sCEi[j]*8))[q];
        }
      }
      GBAR();
      for(int idx=t; idx<kc*8; idx+=256)
        sEW[idx]=__expf(sAL[idx]-sGate[idx&7])*sGate[8+(idx&7)];
      GBAR();
      for(int j=0;j<kc;j++){
        int e=sCEi[j];
        const float4* mp=(const float4*)(g_msg+(size_t)e*1600);
        const float* wj = sEW + j*8;
        for(int i=t;i<400;i+=256){
          float wv=wj[(i&15)>>1];
          float4 v=mp[i];
          float4 a=sA4[i];
          FMA4(a,wv,v);
          sA4[i]=a;
        }
      }
      GBAR();
    }

    // XN = x + agg @ proj_out (FFMA2)
    {
      int r0=rg, r1=rg+16; bool v1=(r1<25);
      const float4* x4g=(const float4*)(x+(size_t)n*1600);
      const ulonglong2* p4=(const ulonglong2*)sPO;
      ulonglong2 a0=tou2(x4g[r0*16+c4]);
      ulonglong2 a1=tou2(v1? x4g[r1*16+c4] : Z4);
      #pragma unroll 8
      for(int k=0;k<64;k++){
        ulonglong2 wv=p4[k*16+c4];
        u64 s0=bc2(sA[r0*64+k]); FMAP(a0,wv,s0);
        if(v1){ u64 s1=bc2(sA[r1*64+k]); FMAP(a1,wv,s1); }
      }
      ((ulonglong2*)sXN)[r0*16+c4]=a0;
      if(v1) ((ulonglong2*)sXN)[r1*16+c4]=a1;
    }
    GBAR();
    if(t<64){
      float s=0.f;
      #pragma unroll
      for(int i=0;i<NC;i++){ float v=sXN[i*64+t]; s=fmaf(v,v,s); }
      sGate[t]=rsqrtf(s*(1.f/25.f)+1e-6f)*sGam[t];
    }
    GBAR();
    {
      float4* sH4=(float4*)sH;
      const float4* xn4=(const float4*)sXN;
      const float4* rv4=(const float4*)sGate;
      for(int i=t;i<400;i+=256){
        int row=i>>4, q=i&15;
        float4 v=xn4[i], r=rv4[q]; MUL4(v,r);
        sH4[row*17+q]=v;
      }
    }
    GBAR();
    float gacc=0.f;
    if(t<128){
      gacc=sGLB[t];
      #pragma unroll 8
      for(int c=0;c<64;c++) gacc=fmaf(sH[c],sGL[c*128+t],gacc);
    }
    GBAR();
    if(t<128) sGate[t]=gacc;
    // F1 = h @ ffn_w1 (+b1 row0) via mma K=64
    {
      float acc[4][4]={};
      #pragma unroll
      for(int kc=0;kc<8;kc++){
        int k0=kc*8;
        unsigned a0=cvt_tf32(sH[rowA*68+k0+cq]);
        unsigned a1=cvt_tf32(sH[rowB*68+k0+cq]);
        unsigned a2=cvt_tf32(sH[rowA*68+k0+cq+4]);
        unsigned a3=cvt_tf32(sH[rowB*68+k0+cq+4]);
        #pragma unroll
        for(int nt=0;nt<4;nt++){
          int nbb=ng*32+nt*8;
          unsigned b0=sW1fp[(k0+cq)*136+nbb+fr];
          unsigned b1=sW1fp[(k0+cq+4)*136+nbb+fr];
          mma_tf32(acc[nt][0],acc[nt][1],acc[nt][2],acc[nt][3],a0,a1,a2,a3,b0,b1);
        }
      }
      #pragma unroll
      for(int nt=0;nt<4;nt++){
        int col=ng*32+nt*8+2*cq;
        if(rowA<25){
          float v0=acc[nt][0], v1=acc[nt][1];
          if(rowA==0){ v0+=sB1[col]; v1+=sB1[col+1]; }
          sF1[rowA*132+col]=v0; sF1[rowA*132+col+1]=v1;
        }
        if(rowB<25){ sF1[rowB*132+col]=acc[nt][2]; sF1[rowB*132+col+1]=acc[nt][3]; }
      }
    }
    GBAR();
    // G2 = silu(to_grid @ F1) (FFMA2)
    {
      int g0=rg8, g1=rg8+8, g2v=rg8+16, g3=rg8+24, g4v=rg8+32; bool v4=(g4v<36);
      const ulonglong2* F4p=(const ulonglong2*)sF1;
      float4* G4=(float4*)sG2;
      ulonglong2 a0=ZP2,a1=ZP2,a2=ZP2,a3=ZP2,a4=ZP2;
      #pragma unroll
      for(int i=0;i<25;i++){
        ulonglong2 fv=F4p[i*33+f4];
        u64 s0=bc2(sTG[g0*25+i]), s1=bc2(sTG[g1*25+i]);
        u64 s2=bc2(sTG[g2v*25+i]), s3=bc2(sTG[g3*25+i]);
        FMAP(a0,fv,s0); FMAP(a1,fv,s1); FMAP(a2,fv,s2); FMAP(a3,fv,s3);
        if(v4){ u64 s4=bc2(sTG[g4v*25+i]); FMAP(a4,fv,s4); }
      }
      G4[g0*32+f4]=silu4(tof4(a0)); G4[g1*32+f4]=silu4(tof4(a1));
      G4[g2v*32+f4]=silu4(tof4(a2)); G4[g3*32+f4]=silu4(tof4(a3));
      if(v4) G4[g4v*32+f4]=silu4(tof4(a4));
    }
    GBAR();
    // F1 := [silu(gate); from_grid @ G2] (FFMA2)
    {
      int r0=rg8, r1=rg8+8, r2=rg8+16;
      const ulonglong2* G4=(const ulonglong2*)sG2;
      ulonglong2 a0=ZP2,a1=ZP2,a2=ZP2,a3=ZP2;
      #pragma unroll 6
      for(int g=0;g<36;g++){
        ulonglong2 gv=G4[g*32+f4];
        if(rg8>0){ u64 s0=bc2(sFG[r0*36+g]); FMAP(a0,gv,s0); }
        u64 s1=bc2(sFG[r1*36+g]), s2=bc2(sFG[r2*36+g]);
        FMAP(a1,gv,s1); FMAP(a2,gv,s2);
        if(rg8==0){ u64 s3=bc2(sFG[24*36+g]); FMAP(a3,gv,s3); }
      }
      if(rg8==0) a0=tou2(silu4(((const float4*)sGate)[f4]));
      ulonglong2* F2v=(ulonglong2*)sF1;
      F2v[r0*33+f4]=a0; F2v[r1*33+f4]=a1; F2v[r2*33+f4]=a2;
      if(rg8==0) F2v[24*33+f4]=a3;
    }
    GBAR();
    // out = XN + F1 @ ffn_w2 (+b2 row0) via mma K=128
    {
      float acc[2][4]={};
      #pragma unroll
      for(int kc=0;kc<16;kc++){
        int k0=kc*8;
        unsigned a0=cvt_tf32(sF1[rowA*132+k0+cq]);
        unsigned a1=cvt_tf32(sF1[rowB*132+k0+cq]);
        unsigned a2=cvt_tf32(sF1[rowA*132+k0+cq+4]);
        unsigned a3=cvt_tf32(sF1[rowB*132+k0+cq+4]);
        #pragma unroll
        for(int nt=0;nt<2;nt++){
          int nbb=ng*16+nt*8;
          unsigned b0=sW2p[(k0+cq)*72+nbb+fr];
          unsigned b1=sW2p[(k0+cq+4)*72+nbb+fr];
          mma_tf32(acc[nt][0],acc[nt][1],acc[nt][2],acc[nt][3],a0,a1,a2,a3,b0,b1);
        }
      }
      float* op=out+(size_t)n*1600;
      #pragma unroll
      for(int nt=0;nt<2;nt++){
        int col=ng*16+nt*8+2*cq;
        if(rowA<25){
          float v0=sXN[rowA*64+col]+acc[nt][0];
          float v1=sXN[rowA*64+col+1]+acc[nt][1];
          if(rowA==0){ v0+=sB2[col]; v1+=sB2[col+1]; }
          *(float2*)(op+rowA*64+col)=make_float2(v0,v1);
        }
        if(rowB<25){
          float v0=sXN[rowB*64+col]+acc[nt][2];
          float v1=sXN[rowB*64+col+1]+acc[nt][3];
          *(float2*)(op+rowB*64+col)=make_float2(v0,v1);
        }
      }
    }
    GBAR();
  }
}

extern "C" void kernel_launch(void* const* d_in, const int* in_sizes, int n_in,
                              void* d_out, int out_size) {
  const float* x    = (const float*)d_in[0];
  const int*   ei   = (const int*)d_in[1];
  const int*   zn   = (const int*)d_in[2];
  const float* ed   = (const float*)d_in[3];
  const float* wigr = (const float*)d_in[4];
  const float* stab = (const float*)d_in[5];
  const float* ttab = (const float*)d_in[6];
  const float* rw1  = (const float*)d_in[7];
  const float* rb1  = (const float*)d_in[8];
  const float* rw2  = (const float*)d_in[9];
  const float* rb2  = (const float*)d_in[10];
  const float* rw3  = (const float*)d_in[11];
  const float* rb3  = (const float*)d_in[12];
  const float* W1   = (const float*)d_in[13];
  const float* W0e  = (const float*)d_in[14];
  const float* adot = (const float*)d_in[15];
  const float* tg   = (const float*)d_in[16];
  const float* fg   = (const float*)d_in[17];
  const float* po   = (const float*)d_in[18];
  const float* gm1  = (const float*)d_in[19];
  const float* gm2  = (const float*)d_in[20];
  const float* glw  = (const float*)d_in[21];
  const float* glb  = (const float*)d_in[22];
  const float* fw1  = (const float*)d_in[23];
  const float* fb1  = (const float*)d_in[24];
  const float* fw2  = (const float*)d_in[25];
  const float* fb2  = (const float*)d_in[26];
  float* out = (float*)d_out;

  void *pcnt;
  cudaGetSymbolAddress(&pcnt, g_cnt);
  cudaMemsetAsync(pcnt, 0, NN*sizeof(int));

  const int RAD_SMEM  = 52864*4;
  const int EDGE_SMEM = (9216+24576+900+900+128 + 2*EPG)*4;
  const int NODE_SMEM = (32392 + 2*NPG)*4;
  cudaFuncSetAttribute(k_rad,  cudaFuncAttributeMaxDynamicSharedMemorySize, RAD_SMEM);
  cudaFuncSetAttribute(k_edge, cudaFuncAttributeMaxDynamicSharedMemorySize, EDGE_SMEM);
  cudaFuncSetAttribute(k_node, cudaFuncAttributeMaxDynamicSharedMemorySize, NODE_SMEM);

  k_rms1<<<(NN+3)/4, dim3(64,4)>>>(x, gm1);
  k_count<<<(EE+255)/256, 256>>>(ei);
  k_scan<<<1, 1024>>>();
  k_fill<<<(EE+255)/256, 256>>>(ei);
  k_rad<<<296, 256, RAD_SMEM>>>(ed, ei, zn, stab, ttab, rw1, rb1, rw2, rb2, rw3, rb3);
  k_edge<<<148, 512, EDGE_SMEM>>>(wigr, ei, W1, W0e, adot, tg, fg);
  k_node<<<148, 512, NODE_SMEM>>>(x, out, po, gm2, glw, glb, fw1, fb1, fw2, fb2, tg, fg);
}

// round 16
// speedup vs baseline: 1.3506x; 1.0031x over previous
#include <cuda_runtime.h>

#define NN 10000
#define EE 50000
#define NC 25
#define EPG 11032
#define NPG 12240

typedef unsigned long long u64;

__constant__ int c_lof[NC] = {0,1,1,1,2,2,2,2,2,3,3,3,3,3,3,3,4,4,4,4,4,4,4,4,4};

__device__ float    g_h[(size_t)NN*1600];
__device__ float    g_r[(size_t)EE*640];
__device__ float    g_msg[(size_t)EE*1600];
__device__ float    g_alpha[EE*8];
__device__ int      g_cnt[NN];
__device__ int      g_rp[NN+1];
__device__ int      g_cur[NN];
__device__ int      g_ce[EE];

__device__ __forceinline__ float silu(float x){ return x/(1.f+__expf(-x)); }
__device__ __forceinline__ float4 silu4(float4 v){
  return make_float4(silu(v.x),silu(v.y),silu(v.z),silu(v.w));
}
__device__ __forceinline__ u64 bc2(float s){
  unsigned i=__float_as_uint(s); u64 r;
  asm("mov.b64 %0,{%1,%1};" : "=l"(r) : "r"(i)); return r;
}
__device__ __forceinline__ void f2(u64&a, u64 v, u64 s){
  asm("fma.rn.f32x2 %0,%1,%2,%0;" : "+l"(a) : "l"(v), "l"(s));
}
__device__ __forceinline__ void m2(u64&a, u64 v){
  asm("mul.rn.f32x2 %0,%0,%1;" : "+l"(a) : "l"(v));
}
__device__ __forceinline__ void padd(u64&a, u64 b){
  asm("add.rn.f32x2 %0,%0,%1;" : "+l"(a) : "l"(b));
}
union F4U { float4 f; ulonglong2 u; };
__device__ __forceinline__ float4 tof4(ulonglong2 a){ F4U u; u.u=a; return u.f; }
__device__ __forceinline__ ulonglong2 tou2(float4 f){ F4U u; u.f=f; return u.u; }
__device__ __forceinline__ unsigned cvt_tf32(float f){
  unsigned u; asm("cvt.rna.tf32.f32 %0,%1;" : "=r"(u) : "f"(f)); return u;
}
__device__ __forceinline__ void mma_tf32(float&c0,float&c1,float&c2,float&c3,
                                         unsigned a0,unsigned a1,unsigned a2,unsigned a3,
                                         unsigned b0,unsigned b1){
  asm("mma.sync.aligned.m16n8k8.row.col.f32.tf32.tf32.f32 "
      "{%0,%1,%2,%3},{%4,%5,%6,%7},{%8,%9},{%0,%1,%2,%3};"
      : "+f"(c0),"+f"(c1),"+f"(c2),"+f"(c3)
      : "r"(a0),"r"(a1),"r"(a2),"r"(a3),"r"(b0),"r"(b1));
}
#define FMAP(a,v,s) { f2((a).x,(v).x,(s)); f2((a).y,(v).y,(s)); }
#define FMA4(a,s,v) { (a).x=fmaf((s),(v).x,(a).x); (a).y=fmaf((s),(v).y,(a).y); \
                      (a).z=fmaf((s),(v).z,(a).z); (a).w=fmaf((s),(v).w,(a).w); }
#define MUL4(a,v)   { (a).x*=(v).x; (a).y*=(v).y; (a).z*=(v).z; (a).w*=(v).w; }
#define Z4 make_float4(0.f,0.f,0.f,0.f)
#define ZP2 {0ull,0ull}
#define GBAR() asm volatile("bar.sync %0, %1;" :: "r"(grp+1), "r"(256) : "memory")

// ---------------- rmsnorm1 ----------------
__global__ void k_rms1(const float* __restrict__ x, const float* __restrict__ gamma){
  int n = blockIdx.x*4 + threadIdx.y;
  if(n >= NN) return;
  int c = threadIdx.x;
  const float* xp = x + (size_t)n*1600 + c;
  float s = 0.f;
  #pragma unroll
  for(int i=0;i<NC;i++){ float v = xp[i*64]; s += v*v; }
  float gm = rsqrtf(s*(1.f/25.f) + 1e-6f) * gamma[c];
  float* hp = g_h + (size_t)n*1600 + c;
  #pragma unroll
  for(int i=0;i<NC;i++) hp[i*64] = xp[i*64]*gm;
}

// ---------------- CSR build ----------------
__global__ void k_count(const int* __restrict__ ei){
  int e = blockIdx.x*256 + threadIdx.x;
  if(e < EE) atomicAdd(&g_cnt[ei[EE+e]], 1);
}
__global__ void k_scan(){
  __shared__ int ps[1024];
  int t = threadIdx.x;
  int v[10]; int s = 0;
  #pragma unroll
  for(int m=0;m<10;m++){ int i=t*10+m; int c=(i<NN)? g_cnt[i]:0; v[m]=s; s+=c; }
  ps[t]=s; __syncthreads();
  for(int off=1; off<1024; off<<=1){
    int val=(t>=off)? ps[t-off]:0; __syncthreads();
    ps[t]+=val; __syncthreads();
  }
  int excl=(t>0)? ps[t-1]:0;
  #pragma unroll
  for(int m=0;m<10;m++){
    int i=t*10+m;
    if(i<NN){ int o=excl+v[m]; g_rp[i]=o; g_cur[i]=o; }
  }
  if(t==0) g_rp[NN]=EE;
}
__global__ void k_fill(const int* __restrict__ ei){
  int e = blockIdx.x*256 + threadIdx.x;
  if(e < EE) g_ce[atomicAdd(&g_cur[ei[EE+e]],1)] = e;
}

// ---------------- radial MLP ----------------
__global__ __launch_bounds__(256,1)
void k_rad(const float* __restrict__ ed, const int* __restrict__ ei,
           const int* __restrict__ zn,
           const float* __restrict__ st, const float* __restrict__ tt,
           const float* __restrict__ w1, const float* __restrict__ b1,
           const float* __restrict__ w2, const float* __restrict__ b2,
           const float* __restrict__ w3, const float* __restrict__ b3)
{
  extern __shared__ float sm[];
  float* sw1=sm; float* sw2=sw1+6144; float* sw3=sw2+4096;
  float* sb1=sw3+40960; float* sb2=sb1+64; float* sb3=sb2+64;
  float* ef=sb3+640; float* h1=ef+384; float* h2=h1+256;
  int tid=threadIdx.x;
  for(int i=tid;i<6144;i+=256)  sw1[i]=w1[i];
  for(int i=tid;i<4096;i+=256)  sw2[i]=w2[i];
  for(int i=tid;i<40960;i+=256) sw3[i]=w3[i];
  if(tid<64){ sb1[tid]=b1[tid]; sb2[tid]=b2[tid]; }
  for(int i=tid;i<640;i+=256)   sb3[i]=b3[i];
  __syncthreads();

  int grp=tid>>6, t=tid&63;
  int q=grp;
  int nm=(q<2)?3:2;
  int m0=q, m1=q+4, m2=q+8;

  int iters=(EE+(int)gridDim.x*4-1)/((int)gridDim.x*4);
  for(int it=0; it<iters; it++){
    int e0=(it*(int)gridDim.x+(int)blockIdx.x)*4;
    int e=e0+grp;
    bool valid=(e<EE);
    if(t<32){
      if(valid){
        int src=ei[e], dst=ei[EE+e];
        ef[grp*96+t]   =ed[(size_t)e*32+t];
        ef[grp*96+32+t]=st[zn[src]*32+t];
        ef[grp*96+64+t]=tt[zn[dst]*32+t];
      } else {
        ef[grp*96+t]=0.f; ef[grp*96+32+t]=0.f; ef[grp*96+64+t]=0.f;
      }
    }
    __syncthreads();
    {
      float acc=sb1[t];
      const float4* ef4=(const float4*)(ef+grp*96);
      #pragma unroll
      for(int k4=0;k4<24;k4++){
        float4 v=ef4[k4];
        acc=fmaf(v.x,sw1[(k4*4+0)*64+t],acc);
        acc=fmaf(v.y,sw1[(k4*4+1)*64+t],acc);
        acc=fmaf(v.z,sw1[(k4*4+2)*64+t],acc);
        acc=fmaf(v.w,sw1[(k4*4+3)*64+t],acc);
      }
      h1[grp*64+t]=silu(acc);
    }
    __syncthreads();
    {
      float acc=sb2[t];
      const float4* h14=(const float4*)(h1+grp*64);
      #pragma unroll
      for(int k4=0;k4<16;k4++){
        float4 v=h14[k4];
        acc=fmaf(v.x,sw2[(k4*4+0)*64+t],acc);
        acc=fmaf(v.y,sw2[(k4*4+1)*64+t],acc);
        acc=fmaf(v.z,sw2[(k4*4+2)*64+t],acc);
        acc=fmaf(v.w,sw2[(k4*4+3)*64+t],acc);
      }
      h2[grp*64+t]=silu(acc);
    }
    __syncthreads();
    {
      float a0[4], a1[4], a2[4];
      #pragma unroll
      for(int ee=0;ee<4;ee++){ a0[ee]=sb3[t+64*m0]; a1[ee]=sb3[t+64*m1]; a2[ee]=(nm==3)?sb3[t+64*m2]:0.f; }
      for(int k=0;k<64;k++){
        float hh0=h2[k], hh1=h2[64+k], hh2v=h2[128+k], hh3=h2[192+k];
        float wA=sw3[k*640+t+64*m0];
        float wB=sw3[k*640+t+64*m1];
        a0[0]=fmaf(wA,hh0,a0[0]); a0[1]=fmaf(wA,hh1,a0[1]); a0[2]=fmaf(wA,hh2v,a0[2]); a0[3]=fmaf(wA,hh3,a0[3]);
        a1[0]=fmaf(wB,hh0,a1[0]); a1[1]=fmaf(wB,hh1,a1[1]); a1[2]=fmaf(wB,hh2v,a1[2]); a1[3]=fmaf(wB,hh3,a1[3]);
        if(nm==3){
          float wC=sw3[k*640+t+64*m2];
          a2[0]=fmaf(wC,hh0,a2[0]); a2[1]=fmaf(wC,hh1,a2[1]); a2[2]=fmaf(wC,hh2v,a2[2]); a2[3]=fmaf(wC,hh3,a2[3]);
        }
      }
      #pragma unroll
      for(int ee=0;ee<4;ee++){
        int eo=e0+ee;
        if(eo<EE){
          g_r[(size_t)eo*640+t+64*m0]=a0[ee];
          g_r[(size_t)eo*640+t+64*m1]=a1[ee];
          if(nm==3) g_r[(size_t)eo*640+t+64*m2]=a2[ee];
        }
      }
    }
    __syncthreads();
  }
}

// ---------------- per-edge kernel: all-mma pipeline ----------------
__global__ __launch_bounds__(512,1)
void k_edge(const float* __restrict__ wigner, const int* __restrict__ ei,
            const float* __restrict__ W1, const float* __restrict__ W0,
            const float* __restrict__ adot, const float* __restrict__ tg,
            const float* __restrict__ fg)
{
  extern __shared__ float sm[];
  unsigned* sW1p = (unsigned*)sm; // 128*72
  float* sW0 = sm+9216;     // 24576
  float* sTG = sW0+24576;   // 900
  float* sFG = sTG+900;     // 900
  float* sAD = sFG+900;     // 128
  float* pe  = sAD+128;     // 2*EPG
  int tid=threadIdx.x;
  for(int i=tid;i<8192;i+=512){ int c=i>>6,h=i&63; sW1p[c*72+h]=cvt_tf32(W1[i]); }
  for(int i=tid;i<24576;i+=512){ int o=i>>7,c=i&127; sW0[i]=W0[c*192+o]; }
  for(int i=tid;i<900;i+=512){ sTG[i]=tg[i]; sFG[i]=fg[i]; }
  if(tid<128) sAD[tid]=adot[tid];
  __syncthreads();

  int grp = tid>>8, t = tid&255;
  float* base  = pe + grp*EPG;
  float* swigA = base;          // 900 (25x36)
  float* swigB = base+900;      // 900
  float* scat  = base+1800;     // 3300 (25x132)
  float* srr   = base+5100;     // 640
  float* sxe   = base+5740;     // 3300 (25x132); reused as sgrid (40x72)
  float* sextra= base+9040;     // 192
  float* smsg  = base+9232;     // 1800 (25x72)
  float* sgrid = sxe;
  float* smact = smsg;

  int w=t>>5, lane=t&31;
  int mt=w&1, ng=w>>1;
  int fr=lane>>2, cq=lane&3;
  int rowA=mt*16+fr, rowB=rowA+8;

  int stride = (int)gridDim.x*2;
  int e = (int)blockIdx.x*2 + grp;
  int p = 0;

  {
    const float* wp=wigner+(size_t)e*625;
    for(int i=t;i<625;i+=256) swigA[(i/25)*36+(i%25)]=wp[i];
    int src=ei[e], dst=ei[EE+e];
    const float4* hs=(const float4*)(g_h+(size_t)src*1600);
    const float4* hd=(const float4*)(g_h+(size_t)dst*1600);
    float4* cat4=(float4*)scat;
    for(int i=t;i<800;i+=256){ int j=i>>5,qq=i&31; cat4[j*33+qq]=(qq<16)?hs[j*16+qq]:hd[j*16+qq-16]; }
    const float4* rp4=(const float4*)(g_r+(size_t)e*640);
    float4* srr4=(float4*)srr;
    for(int i=t;i<160;i+=256) srr4[i]=rp4[i];
  }

  for(; e<EE; e+=stride){
    int en = e + stride; if(en >= EE) en = e;
    float* swig  = p? swigB : swigA;
    float* swigN = p? swigA : swigB;
    GBAR();

    // xe = (wig @ cat)*r[EXPAND]
    {
      float acc[4][4]={};
      #pragma unroll
      for(int kc=0;kc<3;kc++){
        int k0=kc*8;
        unsigned a0=cvt_tf32(swig[rowA*36+k0+cq]);
        unsigned a1=cvt_tf32(swig[rowB*36+k0+cq]);
        unsigned a2=cvt_tf32(swig[rowA*36+k0+cq+4]);
        unsigned a3=cvt_tf32(swig[rowB*36+k0+cq+4]);
        #pragma unroll
        for(int nt=0;nt<4;nt++){
          int nb=ng*32+nt*8;
          unsigned b0=cvt_tf32(scat[(k0+cq)*132+nb+fr]);
          unsigned b1=cvt_tf32(scat[(k0+cq+4)*132+nb+fr]);
          mma_tf32(acc[nt][0],acc[nt][1],acc[nt][2],acc[nt][3],a0,a1,a2,a3,b0,b1);
        }
      }
      float wa0=swig[rowA*36+24], wa1=swig[rowB*36+24];
      int lof0=c_lof[rowA<25?rowA:0], lof1=c_lof[rowB<25?rowB:0];
      #pragma unroll
      for(int nt=0;nt<4;nt++){
        int col=ng*32+nt*8+2*cq;
        float bt0=scat[24*132+col], bt1=scat[24*132+col+1];
        acc[nt][0]=fmaf(wa0,bt0,acc[nt][0]); acc[nt][1]=fmaf(wa0,bt1,acc[nt][1]);
        acc[nt][2]=fmaf(wa1,bt0,acc[nt][2]); acc[nt][3]=fmaf(wa1,bt1,acc[nt][3]);
        if(rowA<25){
          sxe[rowA*132+col]  =acc[nt][0]*srr[lof0*128+col];
          sxe[rowA*132+col+1]=acc[nt][1]*srr[lof0*128+col+1];
        }
        if(rowB<25){
          sxe[rowB*132+col]  =acc[nt][2]*srr[lof1*128+col];
          sxe[rowB*132+col+1]=acc[nt][3]*srr[lof1*128+col+1];
        }
      }
    }
    GBAR();

    // prefetch next edge
    {
      const float* wp=wigner+(size_t)en*625;
      for(int i=t;i<625;i+=256) swigN[(i/25)*36+(i%25)]=wp[i];
      int nsrc=ei[en], ndst=ei[EE+en];
      const float4* hs=(const float4*)(g_h+(size_t)nsrc*1600);
      const float4* hd=(const float4*)(g_h+(size_t)ndst*1600);
      float4* cat4=(float4*)scat;
      for(int i=t;i<800;i+=256){ int j=i>>5,qq=i&31; cat4[j*33+qq]=(qq<16)?hs[j*16+qq]:hd[j*16+qq-16]; }
      const float4* rp4=(const float4*)(g_r+(size_t)en*640);
      float4* srr4=(float4*)srr;
      for(int i=t;i<160;i+=256) srr4[i]=rp4[i];
    }

    // msg = xe @ W1 (mma K=128), extra by t<192
    {
      const float* A0=sxe+rowA*132;
      const float* A1=sxe+rowB*132;
      float acc[2][4]={};
      #pragma unroll
      for(int kc=0;kc<16;kc++){
        int k0=kc*8;
        unsigned a0=cvt_tf32(A0[k0+cq]);
        unsigned a1=cvt_tf32(A1[k0+cq]);
        unsigned a2=cvt_tf32(A0[k0+cq+4]);
        unsigned a3=cvt_tf32(A1[k0+cq+4]);
        #pragma unroll
        for(int nt=0;nt<2;nt++){
          int nb=ng*16+nt*8;
          unsigned b0=sW1p[(k0+cq)*72+nb+fr];
          unsigned b1=sW1p[(k0+cq+4)*72+nb+fr];
          mma_tf32(acc[nt][0],acc[nt][1],acc[nt][2],acc[nt][3],a0,a1,a2,a3,b0,b1);
        }
      }
      #pragma unroll
      for(int nt=0;nt<2;nt++){
        int col=ng*16+nt*8+2*cq;
        if(rowA<25){ smsg[rowA*72+col]=acc[nt][0]; smsg[rowA*72+col+1]=acc[nt][1]; }
        if(rowB<25){ smsg[rowB*72+col]=acc[nt][2]; smsg[rowB*72+col+1]=acc[nt][3]; }
      }
    }
    if(t<192){
      const float4* x0=(const float4*)sxe;
      const float4* wv4=(const float4*)(sW0+t*128);
      float4 acc=Z4;
      #pragma unroll 8
      for(int k=0;k<32;k++){ float4 xv=x0[k], wv=wv4[k];
        acc.x=fmaf(xv.x,wv.x,acc.x); acc.y=fmaf(xv.y,wv.y,acc.y);
        acc.z=fmaf(xv.z,wv.z,acc.z); acc.w=fmaf(xv.w,wv.w,acc.w); }
      sextra[t]=acc.x+acc.y+acc.z+acc.w;
    }
    GBAR();

    // grid = silu(to_grid @ msg) via mma, + alpha by t<8
    if(t<8){
      float acc=0.f;
      #pragma unroll
      for(int a=0;a<16;a++){ float v=sextra[t*16+a]; acc=fmaf(silu(v),sAD[t*16+a],acc); }
      g_alpha[e*8+t]=acc;
    }
    {
      #pragma unroll
      for(int tk=0;tk<2;tk++){
        int task = w + tk*8;
        if(task<12){
          int gmt=task>>2, gnq=task&3;
          int rowG=gmt*16+fr, rowG2=rowG+8;
          float acc[2][4]={};
          #pragma unroll
          for(int kc=0;kc<3;kc++){
            int k0=kc*8;
            unsigned a0=cvt_tf32(sTG[rowG*25+k0+cq]);
            unsigned a1=cvt_tf32(sTG[rowG2*25+k0+cq]);
            unsigned a2=cvt_tf32(sTG[rowG*25+k0+cq+4]);
            unsigned a3=cvt_tf32(sTG[rowG2*25+k0+cq+4]);
            #pragma unroll
            for(int nt=0;nt<2;nt++){
              int nb=gnq*16+nt*8;
              unsigned b0=cvt_tf32(smsg[(k0+cq)*72+nb+fr]);
              unsigned b1=cvt_tf32(smsg[(k0+cq+4)*72+nb+fr]);
              mma_tf32(acc[nt][0],acc[nt][1],acc[nt][2],acc[nt][3],a0,a1,a2,a3,b0,b1);
            }
          }
          float wa0=sTG[rowG*25+24], wa1=sTG[rowG2*25+24];
          #pragma unroll
          for(int nt=0;nt<2;nt++){
            int col=gnq*16+nt*8+2*cq;
            float bt0=smsg[24*72+col], bt1=smsg[24*72+col+1];
            acc[nt][0]=fmaf(wa0,bt0,acc[nt][0]); acc[nt][1]=fmaf(wa0,bt1,acc[nt][1]);
            acc[nt][2]=fmaf(wa1,bt0,acc[nt][2]); acc[nt][3]=fmaf(wa1,bt1,acc[nt][3]);
            if(rowG<36){ sgrid[rowG*72+col]=silu(acc[nt][0]); sgrid[rowG*72+col+1]=silu(acc[nt][1]); }
            if(rowG2<36){ sgrid[rowG2*72+col]=silu(acc[nt][2]); sgrid[rowG2*72+col+1]=silu(acc[nt][3]); }
          }
        }
      }
      { int row=36+(t>>6), col=t&63; sgrid[row*72+col]=0.f; }
    }
    GBAR();

    // mact = [silu(gate); from_grid @ grid] via mma K=40
    {
      float acc[2][4]={};
      #pragma unroll
      for(int kc=0;kc<5;kc++){
        int k0=kc*8;
        unsigned a0=cvt_tf32(sFG[rowA*36+k0+cq]);
        unsigned a1=cvt_tf32(sFG[rowB*36+k0+cq]);
        unsigned a2=cvt_tf32(sFG[rowA*36+k0+cq+4]);
        unsigned a3=cvt_tf32(sFG[rowB*36+k0+cq+4]);
        #pragma unroll
        for(int nt=0;nt<2;nt++){
          int nb=ng*16+nt*8;
          unsigned b0=cvt_tf32(sgrid[(k0+cq)*72+nb+fr]);
          unsigned b1=cvt_tf32(sgrid[(k0+cq+4)*72+nb+fr]);
          mma_tf32(acc[nt][0],acc[nt][1],acc[nt][2],acc[nt][3],a0,a1,a2,a3,b0,b1);
        }
      }
      #pragma unroll
      for(int nt=0;nt<2;nt++){
        int col=ng*16+nt*8+2*cq;
        if(rowA<25){
          float v0=acc[nt][0], v1=acc[nt][1];
          if(rowA==0){ v0=silu(sextra[128+col]); v1=silu(sextra[128+col+1]); }
          smact[rowA*72+col]=v0; smact[rowA*72+col+1]=v1;
        }
        if(rowB<25){ smact[rowB*72+col]=acc[nt][2]; smact[rowB*72+col+1]=acc[nt][3]; }
      }
    }
    GBAR();

    // rotated = wig^T @ mact
    {
      float acc[2][4]={};
      #pragma unroll
      for(int kc=0;kc<3;kc++){
        int k0=kc*8;
        unsigned a0=cvt_tf32(swig[(k0+cq)*36+rowA]);
        unsigned a1=cvt_tf32(swig[(k0+cq)*36+rowB]);
        unsigned a2=cvt_tf32(swig[(k0+cq+4)*36+rowA]);
        unsigned a3=cvt_tf32(swig[(k0+cq+4)*36+rowB]);
        #pragma unroll
        for(int nt=0;nt<2;nt++){
          int nb=ng*16+nt*8;
          unsigned b0=cvt_tf32(smact[(k0+cq)*72+nb+fr]);
          unsigned b1=cvt_tf32(smact[(k0+cq+4)*72+nb+fr]);
          mma_tf32(acc[nt][0],acc[nt][1],acc[nt][2],acc[nt][3],a0,a1,a2,a3,b0,b1);
        }
      }
      float wa0=swig[24*36+rowA], wa1=swig[24*36+rowB];
      float* op=g_msg+(size_t)e*1600;
      #pragma unroll
      for(int nt=0;nt<2;nt++){
        int col=ng*16+nt*8+2*cq;
        float bt0=smact[24*72+col], bt1=smact[24*72+col+1];
        acc[nt][0]=fmaf(wa0,bt0,acc[nt][0]); acc[nt][1]=fmaf(wa0,bt1,acc[nt][1]);
        acc[nt][2]=fmaf(wa1,bt0,acc[nt][2]); acc[nt][3]=fmaf(wa1,bt1,acc[nt][3]);
        if(rowA<25) *(float2*)(op+rowA*64+col)=make_float2(acc[nt][0],acc[nt][1]);
        if(rowB<25) *(float2*)(op+rowB*64+col)=make_float2(acc[nt][2],acc[nt][3]);
      }
    }
    p ^= 1;
  }
}

// ---------------- node: all-mma FFN ----------------
__global__ __launch_bounds__(512,1)
void k_node(const float* __restrict__ x, float* __restrict__ out,
            const float* __restrict__ po, const float* __restrict__ g2w,
            const float* __restrict__ glw, const float* __restrict__ glb,
            const float* __restrict__ fw1, const float* __restrict__ fb1,
            const float* __restrict__ fw2, const float* __restrict__ fb2,
            const float* __restrict__ tg, const float* __restrict__ fg)
{
  extern __shared__ float sm[];
  float* sPO  = sm;                     // 4096
  float* sGL  = sPO+4096;               // 8192
  unsigned* sW1fp=(unsigned*)(sGL+8192);// 8704
  unsigned* sW2p =(unsigned*)(sGL+16896);// 9216
  float* sTG  = sm+30208;               // 900
  float* sFG  = sTG+900;                // 900
  float* sGLB = sFG+900;                // 128
  float* sB1  = sGLB+128;               // 128
  float* sB2  = sB1+128;                // 64
  float* sGam = sB2+64;                 // 64
  float* pn   = sGam+64;                // 2*NPG
  int tid=threadIdx.x;
  for(int i=tid;i<4096;i+=512) sPO[i]=po[i];
  for(int i=tid;i<8192;i+=512) sGL[i]=glw[i];
  for(int i=tid;i<8192;i+=512){ int c=i>>7,f=i&127; sW1fp[c*136+f]=cvt_tf32(fw1[i]); }
  for(int i=tid;i<8192;i+=512){ int f=i>>6,c=i&63; sW2p[f*72+c]=cvt_tf32(fw2[i]); }
  for(int i=tid;i<900;i+=512){ sTG[i]=tg[i]; sFG[i]=fg[i]; }
  if(tid<128){ sGLB[tid]=glb[tid]; sB1[tid]=fb1[tid]; }
  if(tid<64){ sB2[tid]=fb2[tid]; sGam[tid]=g2w[tid]; }
  __syncthreads();

  int grp=tid>>8, t=tid&255;
  float* base = pn + grp*NPG;
  float* sCE  = base;          // 64
  float* sXN  = base+64;       // 1600
  float* sH   = base+1664;     // 1700 (25x68)
  float* sGate= base+3364;     // 128
  float* sF1  = base+3492;     // 3300 (25x132); sAL/sEW alias here (gather phase)
  float* sG2  = base+6792;     // 5440 (40x136); sA alias here
  float* sA   = sG2;
  float* sAL  = sF1;           // 512
  float* sEW  = sF1+512;       // 512
  int* sCEi = (int*)sCE;

  int c4=t&15, rg=t>>4;
  int w=t>>5, lane=t&31;
  int mt=w&1, ng=w>>1;
  int fr=lane>>2, cq=lane&3;
  int rowA=mt*16+fr, rowB=rowA+8;

  for(int nb=blockIdx.x*2; nb<NN; nb+=gridDim.x*2){
    int n = nb + grp;
    int beg=g_rp[n], end=g_rp[n+1];
    int deg=end-beg;
    float4* sA4=(float4*)sA;
    for(int i=t;i<400;i+=256) sA4[i]=Z4;
    if(t<16) sGate[t] = (t<8)? -3.0e38f : 0.f;
    GBAR();

    for(int k0=beg; k0<end; k0+=64){
      int kc=min(64,end-k0);
      for(int idx=t; idx<kc; idx+=256) sCEi[idx]=g_ce[k0+idx];
      GBAR();
      for(int idx=t; idx<kc*2; idx+=256){
        int j=idx>>1, q=idx&1;
        ((float4*)sAL)[j*2+q] = ((const float4*)(g_alpha+(size_t)sCEi[j]*8))[q];
      }
      GBAR();
      if(t<8){
        float m=sGate[t], s=sGate[8+t];
        for(int j=0;j<kc;j++){
          float a=sAL[j*8+t];
          if(a>m){ s=s*__expf(m-a)+1.f; m=a; }
          else    s+=__expf(a-m);
        }
        sGate[t]=m; sGate[8+t]=s;
      }
      GBAR();
    }
    if(t<8) sGate[8+t]=1.f/(sGate[8+t]+1e-8f);
    GBAR();

    for(int k0=beg; k0<end; k0+=64){
      int kc=min(64,end-k0);
      if(deg>64){
        for(int idx=t; idx<kc; idx+=256) sCEi[idx]=g_ce[k0+idx];
        GBAR();
        for(int idx=t; idx<kc*2; idx+=256){
          int j=idx>>1, q=idx&1;
          ((float4*)sAL)[j*2+q] = ((const float4*)(g_alpha+(size_t)sCEi[j]*8))[q];
        }
      }
      GBAR();
      for(int idx=t; idx<kc*8; idx+=256)
        sEW[idx]=__expf(sAL[idx]-sGate[idx&7])*sGate[8+(idx&7)];
      GBAR();
      for(int j=0;j<kc;j++){
        int e=sCEi[j];
        const float4* mp=(const float4*)(g_msg+(size_t)e*1600);
        const float* wj = sEW + j*8;
        for(int i=t;i<400;i+=256){
          float wv=wj[(i&15)>>1];
          float4 v=mp[i];
          float4 a=sA4[i];
          FMA4(a,wv,v);
          sA4[i]=a;
        }
      }
      GBAR();
    }

    // XN = x + agg @ proj_out (FFMA2)
    {
      int r0=rg, r1=rg+16; bool v1=(r1<25);
      const float4* x4g=(const float4*)(x+(size_t)n*1600);
      const ulonglong2* p4=(const ulonglong2*)sPO;
      ulonglong2 a0=tou2(x4g[r0*16+c4]);
      ulonglong2 a1=tou2(v1? x4g[r1*16+c4] : Z4);
      #pragma unroll 8
      for(int k=0;k<64;k++){
        ulonglong2 wv=p4[k*16+c4];
        u64 s0=bc2(sA[r0*64+k]); FMAP(a0,wv,s0);
        if(v1){ u64 s1=bc2(sA[r1*64+k]); FMAP(a1,wv,s1); }
      }
      ((ulonglong2*)sXN)[r0*16+c4]=a0;
      if(v1) ((ulonglong2*)sXN)[r1*16+c4]=a1;
    }
    GBAR();
    if(t<64){
      float s=0.f;
      #pragma unroll
      for(int i=0;i<NC;i++){ float v=sXN[i*64+t]; s=fmaf(v,v,s); }
      sGate[t]=rsqrtf(s*(1.f/25.f)+1e-6f)*sGam[t];
    }
    GBAR();
    {
      float4* sH4=(float4*)sH;
      const float4* xn4=(const float4*)sXN;
      const float4* rv4=(const float4*)sGate;
      for(int i=t;i<400;i+=256){
        int row=i>>4, q=i&15;
        float4 v=xn4[i], r=rv4[q]; MUL4(v,r);
        sH4[row*17+q]=v;
      }
    }
    GBAR();
    float gacc=0.f;
    if(t<128){
      gacc=sGLB[t];
      #pragma unroll 8
      for(int c=0;c<64;c++) gacc=fmaf(sH[c],sGL[c*128+t],gacc);
    }
    GBAR();
    if(t<128) sGate[t]=gacc;
    // F1 = h @ ffn_w1 (+b1 row0) via mma K=64
    {
      float acc[4][4]={};
      #pragma unroll
      for(int kc=0;kc<8;kc++){
        int k0=kc*8;
        unsigned a0=cvt_tf32(sH[rowA*68+k0+cq]);
        unsigned a1=cvt_tf32(sH[rowB*68+k0+cq]);
        unsigned a2=cvt_tf32(sH[rowA*68+k0+cq+4]);
        unsigned a3=cvt_tf32(sH[rowB*68+k0+cq+4]);
        #pragma unroll
        for(int nt=0;nt<4;nt++){
          int nbb=ng*32+nt*8;
          unsigned b0=sW1fp[(k0+cq)*136+nbb+fr];
          unsigned b1=sW1fp[(k0+cq+4)*136+nbb+fr];
          mma_tf32(acc[nt][0],acc[nt][1],acc[nt][2],acc[nt][3],a0,a1,a2,a3,b0,b1);
        }
      }
      #pragma unroll
      for(int nt=0;nt<4;nt++){
        int col=ng*32+nt*8+2*cq;
        if(rowA<25){
          float v0=acc[nt][0], v1=acc[nt][1];
          if(rowA==0){ v0+=sB1[col]; v1+=sB1[col+1]; }
          sF1[rowA*132+col]=v0; sF1[rowA*132+col+1]=v1;
        }
        if(rowB<25){ sF1[rowB*132+col]=acc[nt][2]; sF1[rowB*132+col+1]=acc[nt][3]; }
      }
    }
    GBAR();
    // G2 = silu(to_grid @ F1) via mma: 24 tasks (3 mt x 8 nq), 3 per warp
    {
      #pragma unroll
      for(int tk=0;tk<3;tk++){
        int task = w + tk*8;     // 0..23
        int gmt=task>>3, gnq=task&7;
        int rowG=gmt*16+fr, rowG2=rowG+8;
        float acc[2][4]={};
        #pragma unroll
        for(int kc=0;kc<3;kc++){
          int k0=kc*8;
          unsigned a0=cvt_tf32(sTG[rowG*25+k0+cq]);
          unsigned a1=cvt_tf32(sTG[rowG2*25+k0+cq]);
          unsigned a2=cvt_tf32(sTG[rowG*25+k0+cq+4]);
          unsigned a3=cvt_tf32(sTG[rowG2*25+k0+cq+4]);
          #pragma unroll
          for(int nt=0;nt<2;nt++){
            int nbb=gnq*16+nt*8;
            unsigned b0=cvt_tf32(sF1[(k0+cq)*132+nbb+fr]);
            unsigned b1=cvt_tf32(sF1[(k0+cq+4)*132+nbb+fr]);
            mma_tf32(acc[nt][0],acc[nt][1],acc[nt][2],acc[nt][3],a0,a1,a2,a3,b0,b1);
          }
        }
        float wa0=sTG[rowG*25+24], wa1=sTG[rowG2*25+24];
        #pragma unroll
        for(int nt=0;nt<2;nt++){
          int col=gnq*16+nt*8+2*cq;
          float bt0=sF1[24*132+col], bt1=sF1[24*132+col+1];
          acc[nt][0]=fmaf(wa0,bt0,acc[nt][0]); acc[nt][1]=fmaf(wa0,bt1,acc[nt][1]);
          acc[nt][2]=fmaf(wa1,bt0,acc[nt][2]); acc[nt][3]=fmaf(wa1,bt1,acc[nt][3]);
          if(rowG<36){ sG2[rowG*136+col]=silu(acc[nt][0]); sG2[rowG*136+col+1]=silu(acc[nt][1]); }
          if(rowG2<36){ sG2[rowG2*136+col]=silu(acc[nt][2]); sG2[rowG2*136+col+1]=silu(acc[nt][3]); }
        }
      }
      { int row=36+(t>>6), col=t&63; sG2[row*136+col]=0.f; sG2[row*136+col+64]=0.f; }
    }
    GBAR();
    // F1 := [silu(gate); from_grid @ G2] via mma K=40
    {
      float acc[4][4]={};
      #pragma unroll
      for(int kc=0;kc<5;kc++){
        int k0=kc*8;
        unsigned a0=cvt_tf32(sFG[rowA*36+k0+cq]);
        unsigned a1=cvt_tf32(sFG[rowB*36+k0+cq]);
        unsigned a2=cvt_tf32(sFG[rowA*36+k0+cq+4]);
        unsigned a3=cvt_tf32(sFG[rowB*36+k0+cq+4]);
        #pragma unroll
        for(int nt=0;nt<4;nt++){
          int nbb=ng*32+nt*8;
          unsigned b0=cvt_tf32(sG2[(k0+cq)*136+nbb+fr]);
          unsigned b1=cvt_tf32(sG2[(k0+cq+4)*136+nbb+fr]);
          mma_tf32(acc[nt][0],acc[nt][1],acc[nt][2],acc[nt][3],a0,a1,a2,a3,b0,b1);
        }
      }
      #pragma unroll
      for(int nt=0;nt<4;nt++){
        int col=ng*32+nt*8+2*cq;
        if(rowA<25){
          float v0=acc[nt][0], v1=acc[nt][1];
          if(rowA==0){ v0=silu(sGate[col]); v1=silu(sGate[col+1]); }
          sF1[rowA*132+col]=v0; sF1[rowA*132+col+1]=v1;
        }
        if(rowB<25){ sF1[rowB*132+col]=acc[nt][2]; sF1[rowB*132+col+1]=acc[nt][3]; }
      }
    }
    GBAR();
    // out = XN + F1 @ ffn_w2 (+b2 row0) via mma K=128
    {
      float acc[2][4]={};
      #pragma unroll
      for(int kc=0;kc<16;kc++){
        int k0=kc*8;
        unsigned a0=cvt_tf32(sF1[rowA*132+k0+cq]);
        unsigned a1=cvt_tf32(sF1[rowB*132+k0+cq]);
        unsigned a2=cvt_tf32(sF1[rowA*132+k0+cq+4]);
        unsigned a3=cvt_tf32(sF1[rowB*132+k0+cq+4]);
        #pragma unroll
        for(int nt=0;nt<2;nt++){
          int nbb=ng*16+nt*8;
          unsigned b0=sW2p[(k0+cq)*72+nbb+fr];
          unsigned b1=sW2p[(k0+cq+4)*72+nbb+fr];
          mma_tf32(acc[nt][0],acc[nt][1],acc[nt][2],acc[nt][3],a0,a1,a2,a3,b0,b1);
        }
      }
      float* op=out+(size_t)n*1600;
      #pragma unroll
      for(int nt=0;nt<2;nt++){
        int col=ng*16+nt*8+2*cq;
        if(rowA<25){
          float v0=sXN[rowA*64+col]+acc[nt][0];
          float v1=sXN[rowA*64+col+1]+acc[nt][1];
          if(rowA==0){ v0+=sB2[col]; v1+=sB2[col+1]; }
          *(float2*)(op+rowA*64+col)=make_float2(v0,v1);
        }
        if(rowB<25){
          float v0=sXN[rowB*64+col]+acc[nt][2];
          float v1=sXN[rowB*64+col+1]+acc[nt][3];
          *(float2*)(op+rowB*64+col)=make_float2(v0,v1);
        }
      }
    }
    GBAR();
  }
}

extern "C" void kernel_launch(void* const* d_in, const int* in_sizes, int n_in,
                              void* d_out, int out_size) {
  const float* x    = (const float*)d_in[0];
  const int*   ei   = (const int*)d_in[1];
  const int*   zn   = (const int*)d_in[2];
  const float* ed   = (const float*)d_in[3];
  const float* wigr = (const float*)d_in[4];
  const float* stab = (const float*)d_in[5];
  const float* ttab = (const float*)d_in[6];
  const float* rw1  = (const float*)d_in[7];
  const float* rb1  = (const float*)d_in[8];
  const float* rw2  = (const float*)d_in[9];
  const float* rb2  = (const float*)d_in[10];
  const float* rw3  = (const float*)d_in[11];
  const float* rb3  = (const float*)d_in[12];
  const float* W1   = (const float*)d_in[13];
  const float* W0e  = (const float*)d_in[14];
  const float* adot = (const float*)d_in[15];
  const float* tg   = (const float*)d_in[16];
  const float* fg   = (const float*)d_in[17];
  const float* po   = (const float*)d_in[18];
  const float* gm1  = (const float*)d_in[19];
  const float* gm2  = (const float*)d_in[20];
  const float* glw  = (const float*)d_in[21];
  const float* glb  = (const float*)d_in[22];
  const float* fw1  = (const float*)d_in[23];
  const float* fb1  = (const float*)d_in[24];
  const float* fw2  = (const float*)d_in[25];
  const float* fb2  = (const float*)d_in[26];
  float* out = (float*)d_out;

  void *pcnt;
  cudaGetSymbolAddress(&pcnt, g_cnt);
  cudaMemsetAsync(pcnt, 0, NN*sizeof(int));

  const int RAD_SMEM  = 52864*4;
  const int EDGE_SMEM = (9216+24576+900+900+128 + 2*EPG)*4;
  const int NODE_SMEM = (32392 + 2*NPG)*4;   // 227488
  cudaFuncSetAttribute(k_rad,  cudaFuncAttributeMaxDynamicSharedMemorySize, RAD_SMEM);
  cudaFuncSetAttribute(k_edge, cudaFuncAttributeMaxDynamicSharedMemorySize, EDGE_SMEM);
  cudaFuncSetAttribute(k_node, cudaFuncAttributeMaxDynamicSharedMemorySize, NODE_SMEM);

  k_rms1<<<(NN+3)/4, dim3(64,4)>>>(x, gm1);
  k_count<<<(EE+255)/256, 256>>>(ei);
  k_scan<<<1, 1024>>>();
  k_fill<<<(EE+255)/256, 256>>>(ei);
  k_rad<<<296, 256, RAD_SMEM>>>(ed, ei, zn, stab, ttab, rw1, rb1, rw2, rb2, rw3, rb3);
  k_edge<<<148, 512, EDGE_SMEM>>>(wigr, ei, W1, W0e, adot, tg, fg);
  k_node<<<148, 512, NODE_SMEM>>>(x, out, po, gm2, glw, glb, fw1, fb1, fw2, fb2, tg, fg);
}